// round 2
// baseline (speedup 1.0000x reference)
#include <cuda_runtime.h>

// Problem constants: B=4, C=64, T=8, H=32, W=32, O=64
#define B_   4
#define TT_  8
#define N_   32          // B*T
#define C_   64
#define HW   1024        // H*W
#define CHW  65536       // C*HW

// ---------------- scratch (device globals; no allocation) ----------------
__device__ float g_rq[N_*C_*HW];               // 8 MB   (n,c,i) relu(q)
__device__ float g_rk[N_*C_*HW];               // 8 MB
__device__ float g_rv[N_*C_*HW];               // 8 MB
__device__ float g_gc[N_*C_*C_];               // 512 KB channel scores / softmaxed
__device__ float g_ms[(size_t)N_*HW*HW];       // 128 MB exp(spatial scores)
__device__ float g_inv[HW*HW];                 // 4 MB   1/sum_n exp(scores)
__device__ float g_s [N_*C_*HW];               // 8 MB   a_c + a_s
__device__ float g_xe[N_*C_*HW];               // 8 MB   relu(tconv3)
__device__ float g_mt[B_*TT_*TT_];             // temporal scores

// ---------------- K1: q/k/v = relu(W x + b), layout (n,c,i) ----------------
__global__ __launch_bounds__(256) void k_qkv(
    const float* __restrict__ x,
    const float* __restrict__ wq, const float* __restrict__ bq,
    const float* __restrict__ wk, const float* __restrict__ bk,
    const float* __restrict__ wv, const float* __restrict__ bv)
{
    int n = blockIdx.x;
    int b = n >> 3, t = n & 7;
    int i = (blockIdx.y << 8) + threadIdx.x;

    // x[b][c][t][i], c-stride = T*HW
    const float* xp = x + ((size_t)b * C_ * TT_ + t) * HW + i;
    float xr[C_];
#pragma unroll
    for (int c = 0; c < C_; c++) xr[c] = xp[(size_t)c * TT_ * HW];

    __shared__ float sw[C_*C_];
    __shared__ float sb[C_];

    for (int p = 0; p < 3; p++) {
        const float* W  = (p == 0) ? wq : (p == 1) ? wk : wv;
        const float* Bb = (p == 0) ? bq : (p == 1) ? bk : bv;
        float*       Op = (p == 0) ? g_rq : (p == 1) ? g_rk : g_rv;
        __syncthreads();
        for (int k = threadIdx.x; k < C_*C_; k += 256) sw[k] = W[k];
        if (threadIdx.x < C_) sb[threadIdx.x] = Bb[threadIdx.x];
        __syncthreads();
        float* op = Op + (n * C_) * HW + i;
        for (int o = 0; o < C_; o++) {
            float acc = sb[o];
#pragma unroll
            for (int c = 0; c < C_; c++) acc = fmaf(sw[o*C_ + c], xr[c], acc);
            op[o * HW] = fmaxf(acc, 0.f);
        }
    }
}

// ---------------- K2: channel scores G[n][c][d] = sum_i q[n,c,i] k[n,d,i] ----------------
__global__ __launch_bounds__(256) void k_gc()
{
    int n = blockIdx.x;
    __shared__ float sq[C_*65];   // padded stride 65
    __shared__ float sk[C_*65];
    int tid = threadIdx.x;
    int ty = tid >> 4, tx = tid & 15;

    float acc[4][4];
#pragma unroll
    for (int r = 0; r < 4; r++)
#pragma unroll
        for (int s2 = 0; s2 < 4; s2++) acc[r][s2] = 0.f;

    for (int it = 0; it < 16; it++) {
        __syncthreads();
        for (int k = tid; k < C_*64; k += 256) {
            int c = k >> 6, ii = k & 63;
            sq[c*65 + ii] = g_rq[(n*C_ + c)*HW + it*64 + ii];
            sk[c*65 + ii] = g_rk[(n*C_ + c)*HW + it*64 + ii];
        }
        __syncthreads();
        for (int ii = 0; ii < 64; ii++) {
            float a[4], bb[4];
#pragma unroll
            for (int r = 0; r < 4; r++)  a[r]  = sq[(ty*4 + r)*65 + ii];
#pragma unroll
            for (int s2 = 0; s2 < 4; s2++) bb[s2] = sk[(tx*4 + s2)*65 + ii];
#pragma unroll
            for (int r = 0; r < 4; r++)
#pragma unroll
                for (int s2 = 0; s2 < 4; s2++) acc[r][s2] = fmaf(a[r], bb[s2], acc[r][s2]);
        }
    }
#pragma unroll
    for (int r = 0; r < 4; r++)
#pragma unroll
        for (int s2 = 0; s2 < 4; s2++)
            g_gc[n*C_*C_ + (ty*4 + r)*C_ + tx*4 + s2] = acc[r][s2];
}

// ---------------- K3a: softmax over n of G (axis 0) ----------------
__global__ void k_gc_softmax()
{
    int cd = blockIdx.x * 256 + threadIdx.x;   // 0..4095
    float v[N_];
    float mx = -1e30f;
#pragma unroll
    for (int n = 0; n < N_; n++) { v[n] = g_gc[n*4096 + cd]; mx = fmaxf(mx, v[n]); }
    float s = 0.f;
#pragma unroll
    for (int n = 0; n < N_; n++) { v[n] = __expf(v[n] - mx); s += v[n]; }
    float inv = 1.f / s;
#pragma unroll
    for (int n = 0; n < N_; n++) g_gc[n*4096 + cd] = v[n] * inv;
}

// ---------------- K3b: a_c[n,c,i] = sum_d m_c[n,c,d] v[n,d,i] -> g_s ----------------
__global__ __launch_bounds__(256) void k_ac()
{
    int n = blockIdx.x;
    int i = (blockIdx.y << 8) + threadIdx.x;
    __shared__ float sm[C_*C_];
    for (int k = threadIdx.x; k < C_*C_; k += 256) sm[k] = g_gc[n*4096 + k];
    __syncthreads();
    float vr[C_];
#pragma unroll
    for (int d = 0; d < C_; d++) vr[d] = g_rv[(n*C_ + d)*HW + i];
    for (int c = 0; c < C_; c++) {
        float acc = 0.f;
#pragma unroll
        for (int d = 0; d < C_; d++) acc = fmaf(sm[c*C_ + d], vr[d], acc);
        g_s[(n*C_ + c)*HW + i] = acc;
    }
}

// ---------------- K4: e[n,i,j] = exp(sum_c q[n,c,i] k[n,c,j]) ----------------
// 128x128 output tile per block, 8x8 micro-tile, c chunked by 32 (32 KB smem).
__global__ __launch_bounds__(256) void k_ms()
{
    int n  = blockIdx.z;
    int i0 = blockIdx.x << 7, j0 = blockIdx.y << 7;
    __shared__ float sq[32*128];
    __shared__ float sk[32*128];
    int tid = threadIdx.x, ty = tid >> 4, tx = tid & 15;

    float acc[8][8];
#pragma unroll
    for (int r = 0; r < 8; r++)
#pragma unroll
        for (int s2 = 0; s2 < 8; s2++) acc[r][s2] = 0.f;

    for (int cc = 0; cc < C_; cc += 32) {
        __syncthreads();
        const float* qp = g_rq + (n*C_ + cc)*HW + i0;
        const float* kp = g_rk + (n*C_ + cc)*HW + j0;
        for (int k = tid; k < 1024; k += 256) {
            int c = k >> 5, f = k & 31;
            ((float4*)sq)[k] = ((const float4*)(qp + c*HW))[f];
            ((float4*)sk)[k] = ((const float4*)(kp + c*HW))[f];
        }
        __syncthreads();
#pragma unroll
        for (int c = 0; c < 32; c++) {
            float4 a0 = *(const float4*)&sq[c*128 + ty*8];
            float4 a1 = *(const float4*)&sq[c*128 + ty*8 + 4];
            float4 b0 = *(const float4*)&sk[c*128 + tx*8];
            float4 b1 = *(const float4*)&sk[c*128 + tx*8 + 4];
            float a[8] = {a0.x,a0.y,a0.z,a0.w,a1.x,a1.y,a1.z,a1.w};
            float b[8] = {b0.x,b0.y,b0.z,b0.w,b1.x,b1.y,b1.z,b1.w};
#pragma unroll
            for (int r = 0; r < 8; r++)
#pragma unroll
                for (int s2 = 0; s2 < 8; s2++) acc[r][s2] = fmaf(a[r], b[s2], acc[r][s2]);
        }
    }
    float* outp = g_ms + ((size_t)n << 20) + (size_t)(i0 + ty*8)*HW + j0 + tx*8;
#pragma unroll
    for (int r = 0; r < 8; r++) {
        float4 o0 = make_float4(__expf(acc[r][0]), __expf(acc[r][1]),
                                __expf(acc[r][2]), __expf(acc[r][3]));
        float4 o1 = make_float4(__expf(acc[r][4]), __expf(acc[r][5]),
                                __expf(acc[r][6]), __expf(acc[r][7]));
        *(float4*)(outp + (size_t)r*HW)     = o0;
        *(float4*)(outp + (size_t)r*HW + 4) = o1;
    }
}

// ---------------- K5: g_inv[ij] = 1 / sum_n e[n,ij] ----------------
__global__ __launch_bounds__(256) void k_sum()
{
    size_t ij4 = (size_t)blockIdx.x * 256 + threadIdx.x;   // float4 index, 0..262143
    const float4* base = (const float4*)g_ms;
    float4 s = make_float4(0.f, 0.f, 0.f, 0.f);
#pragma unroll
    for (int n = 0; n < N_; n++) {
        float4 v = base[((size_t)n << 18) + ij4];
        s.x += v.x; s.y += v.y; s.z += v.z; s.w += v.w;
    }
    float4 r = make_float4(1.f/s.x, 1.f/s.y, 1.f/s.z, 1.f/s.w);
    ((float4*)g_inv)[ij4] = r;
}

// ---------------- K6: a_s[n,c,i] = sum_j (e*inv)[n,i,j] v[n,c,j]; g_s += a_s ----------
// 64c x 64i tile, 128 threads, 4c x 8i micro, j chunked by 32.
__global__ __launch_bounds__(128) void k_as()
{
    int n  = blockIdx.y;
    int i0 = blockIdx.x << 6;
    __shared__ float sv[C_*37];     // [c][j] pad 37
    __shared__ float se[32*72];     // [j][i] pad 72 (16B aligned rows)
    int tid = threadIdx.x;
    int ty = tid >> 3, tx = tid & 7;   // ty 0..15 -> c0=ty*4 ; tx 0..7 -> i=tx*8

    float acc[4][8];
#pragma unroll
    for (int r = 0; r < 4; r++)
#pragma unroll
        for (int s2 = 0; s2 < 8; s2++) acc[r][s2] = 0.f;

    const float* msp = g_ms + ((size_t)n << 20);
    for (int jc = 0; jc < 32; jc++) {
        int j0 = jc << 5;
        __syncthreads();
        // v tile: [c][j], straight (conflict-free stores)
        for (int k = tid; k < 2048; k += 128) {
            int c = k >> 5, jj = k & 31;
            sv[c*37 + jj] = g_rv[(n*C_ + c)*HW + j0 + jj];
        }
        // P tile: transpose-on-load with fused softmax normalize
        for (int k = tid; k < 2048; k += 128) {
            int ii = k >> 5, jj = k & 31;
            int gi = i0 + ii;
            se[jj*72 + ii] = msp[(size_t)gi*HW + j0 + jj] * g_inv[gi*HW + j0 + jj];
        }
        __syncthreads();
#pragma unroll
        for (int j = 0; j < 32; j++) {
            float a0 = sv[(ty*4 + 0)*37 + j];
            float a1 = sv[(ty*4 + 1)*37 + j];
            float a2 = sv[(ty*4 + 2)*37 + j];
            float a3 = sv[(ty*4 + 3)*37 + j];
            float4 b0 = *(const float4*)&se[j*72 + tx*8];
            float4 b1 = *(const float4*)&se[j*72 + tx*8 + 4];
            float b[8] = {b0.x,b0.y,b0.z,b0.w,b1.x,b1.y,b1.z,b1.w};
            float a[4] = {a0,a1,a2,a3};
#pragma unroll
            for (int r = 0; r < 4; r++)
#pragma unroll
                for (int s2 = 0; s2 < 8; s2++) acc[r][s2] = fmaf(a[r], b[s2], acc[r][s2]);
        }
    }
    // accumulate onto a_c already in g_s
#pragma unroll
    for (int r = 0; r < 4; r++) {
        int c = ty*4 + r;
        float* gp = &g_s[(n*C_ + c)*HW + i0 + tx*8];
        float4 o0 = *(float4*)gp;
        float4 o1 = *(float4*)(gp + 4);
        o0.x += acc[r][0]; o0.y += acc[r][1]; o0.z += acc[r][2]; o0.w += acc[r][3];
        o1.x += acc[r][4]; o1.y += acc[r][5]; o1.z += acc[r][6]; o1.w += acc[r][7];
        *(float4*)gp = o0;
        *(float4*)(gp + 4) = o1;
    }
}

// ---------------- K7: Xe = relu(tconv3(s)) : (3,1,1) kernel, pad 1 on t ----------------
__global__ __launch_bounds__(256) void k_tconv(const float* __restrict__ wX,
                                               const float* __restrict__ bX)
{
    int n = blockIdx.x;
    int b = n >> 3, t = n & 7;
    int i = (blockIdx.y << 8) + threadIdx.x;
    __shared__ float sw[32*64];

    for (int h = 0; h < 2; h++) {
        float acc[32];
#pragma unroll
        for (int o = 0; o < 32; o++) acc[o] = bX[h*32 + o];
        for (int kt = 0; kt < 3; kt++) {
            int t2 = t + kt - 1;
            __syncthreads();
            for (int k = threadIdx.x; k < 2048; k += 256) {
                int o = k >> 6, c = k & 63;
                sw[k] = wX[((h*32 + o)*64 + c)*3 + kt];
            }
            __syncthreads();
            if (t2 < 0 || t2 >= TT_) continue;   // uniform per block
            float xr[64];
#pragma unroll
            for (int c = 0; c < 64; c++) xr[c] = g_s[((b*TT_ + t2)*C_ + c)*HW + i];
            for (int o = 0; o < 32; o++) {
                float a = acc[o];
#pragma unroll
                for (int c = 0; c < 64; c++) a = fmaf(sw[o*64 + c], xr[c], a);
                acc[o] = a;
            }
        }
        for (int o = 0; o < 32; o++)
            g_xe[(n*C_ + h*32 + o)*HW + i] = fmaxf(acc[o], 0.f);
        __syncthreads();
    }
}

// ---------------- K8a: temporal scores m_t[b,t,s] = <Xe[b,t,:], Xe[b,s,:]> ----------------
__global__ void k_mt()
{
    int idx = blockIdx.x;            // b*64 + t*8 + s
    int b = idx >> 6, ts = idx & 63;
    int t = ts >> 3, s2 = ts & 7;
    const float* qp = g_xe + (size_t)(b*TT_ + t)  * CHW;
    const float* kp = g_xe + (size_t)(b*TT_ + s2) * CHW;
    float sum = 0.f;
    for (int d = threadIdx.x; d < CHW; d += 256) sum = fmaf(qp[d], kp[d], sum);
    __shared__ float red[256];
    red[threadIdx.x] = sum;
    __syncthreads();
    for (int off = 128; off > 0; off >>= 1) {
        if (threadIdx.x < off) red[threadIdx.x] += red[threadIdx.x + off];
        __syncthreads();
    }
    if (threadIdx.x == 0) g_mt[idx] = red[0];
}

// ---------------- K8b: softmax over b (axis 0) of m_t ----------------
__global__ void k_mt_softmax()
{
    int ts = threadIdx.x;  // 0..63
    float v[B_];
    float mx = -1e30f;
#pragma unroll
    for (int b = 0; b < B_; b++) { v[b] = g_mt[b*64 + ts]; mx = fmaxf(mx, v[b]); }
    float s = 0.f;
#pragma unroll
    for (int b = 0; b < B_; b++) { v[b] = __expf(v[b] - mx); s += v[b]; }
    float inv = 1.f / s;
#pragma unroll
    for (int b = 0; b < B_; b++) g_mt[b*64 + ts] = v[b] * inv;
}

// ---------------- K8c: out[b,c,t,i] = sum_s m_t[b,t,s] v[(b,s),c,i] ----------------
__global__ __launch_bounds__(256) void k_out(float* __restrict__ out)
{
    int bct = blockIdx.x;            // (b*64+c)*8 + t, 2048 blocks
    int t  = bct & 7;
    int bc = bct >> 3;
    int b  = bc >> 6, c = bc & 63;
    __shared__ float smt[8];
    if (threadIdx.x < 8) smt[threadIdx.x] = g_mt[b*64 + t*8 + threadIdx.x];
    __syncthreads();
    for (int i = threadIdx.x; i < HW; i += 256) {
        float acc = 0.f;
#pragma unroll
        for (int s2 = 0; s2 < 8; s2++)
            acc = fmaf(smt[s2], g_rv[((b*TT_ + s2)*C_ + c)*HW + i], acc);
        out[(size_t)bct * HW + i] = acc;
    }
}

// ---------------- launch ----------------
extern "C" void kernel_launch(void* const* d_in, const int* in_sizes, int n_in,
                              void* d_out, int out_size)
{
    const float* x  = (const float*)d_in[0];
    const float* wq = (const float*)d_in[1];
    const float* bq = (const float*)d_in[2];
    const float* wk = (const float*)d_in[3];
    const float* bk = (const float*)d_in[4];
    const float* wv = (const float*)d_in[5];
    const float* bv = (const float*)d_in[6];
    const float* wX = (const float*)d_in[7];
    const float* bX = (const float*)d_in[8];
    float* out = (float*)d_out;
    (void)in_sizes; (void)n_in; (void)out_size;

    k_qkv<<<dim3(N_, 4), 256>>>(x, wq, bq, wk, bk, wv, bv);
    k_gc<<<N_, 256>>>();
    k_gc_softmax<<<16, 256>>>();
    k_ac<<<dim3(N_, 4), 256>>>();
    k_ms<<<dim3(8, 8, N_), 256>>>();
    k_sum<<<1024, 256>>>();
    k_as<<<dim3(16, N_), 128>>>();
    k_tconv<<<dim3(N_, 4), 256>>>(wX, bX);
    k_mt<<<256, 256>>>();
    k_mt_softmax<<<1, 64>>>();
    k_out<<<2048, 256>>>(out);
}

// round 3
// speedup vs baseline: 1.2409x; 1.2409x over previous
#include <cuda_runtime.h>

// Problem constants: B=4, C=64, T=8, H=32, W=32, O=64
#define B_   4
#define TT_  8
#define N_   32          // B*T
#define C_   64
#define HW   1024        // H*W
#define CHW  65536       // C*HW

// ---------------- f32x2 helpers ----------------
__device__ __forceinline__ unsigned long long pack2(float a, float b) {
    unsigned long long r;
    asm("mov.b64 %0,{%1,%2};" : "=l"(r) : "f"(a), "f"(b));
    return r;
}
__device__ __forceinline__ void fma2(unsigned long long& d,
                                     unsigned long long a, unsigned long long b) {
    asm("fma.rn.f32x2 %0,%1,%2,%0;" : "+l"(d) : "l"(a), "l"(b));
}
__device__ __forceinline__ float2 unpack2(unsigned long long v) {
    float2 f;
    asm("mov.b64 {%0,%1},%2;" : "=f"(f.x), "=f"(f.y) : "l"(v));
    return f;
}
__device__ __forceinline__ void f4_to_2ull(float4 v, unsigned long long& lo,
                                           unsigned long long& hi) {
    lo = pack2(v.x, v.y);
    hi = pack2(v.z, v.w);
}

// ---------------- scratch (device globals; no allocation) ----------------
__device__ float g_rq[N_*C_*HW];               // 8 MB   (n,c,i) relu(q)
__device__ float g_rk[N_*C_*HW];               // 8 MB
__device__ float g_rv[N_*C_*HW];               // 8 MB
__device__ float g_gcp[8*N_*C_*C_];            // 4 MB   channel-score i-partials
__device__ float g_gc[N_*C_*C_];               // 512 KB softmaxed channel attn
__device__ float g_ms[(size_t)N_*HW*HW];       // 128 MB exp(spatial scores)
__device__ float g_inv[HW*HW];                 // 4 MB   1/sum_n exp
__device__ float g_s [N_*C_*HW];               // 8 MB   a_c + a_s
__device__ float g_xe[N_*C_*HW];               // 8 MB   relu(tconv3)
__device__ float g_mtp[B_*8*64];               // temporal score partials
__device__ float g_mt[B_*TT_*TT_];             // temporal softmax

// ============ K1: q/k/v = relu(W x + b) — FMA2 GEMM, grid (N_,8) x 256 ============
// dyn smem: sx[64c][128i] (8192 f) + sw[64o*64c] (4096 f) = 48 KB
__global__ __launch_bounds__(256) void k_qkv(
    const float* __restrict__ x,
    const float* __restrict__ wq, const float* __restrict__ bq,
    const float* __restrict__ wk, const float* __restrict__ bk,
    const float* __restrict__ wv, const float* __restrict__ bv)
{
    extern __shared__ float dyn[];
    float* sx = dyn;            // 64 x 128
    float* sw = dyn + 8192;     // 64o x 64c
    int n = blockIdx.x, b = n >> 3, t = n & 7;
    int i0 = blockIdx.y << 7;
    int tid = threadIdx.x, ty = tid >> 4, tx = tid & 15;
    int o0 = ty * 4;

    // load x tile once
    for (int k = tid; k < 2048; k += 256) {
        int c = k >> 5, f = k & 31;
        ((float4*)sx)[k] =
            ((const float4*)(x + ((size_t)(b*C_ + c)*TT_ + t)*HW + i0))[f];
    }

    for (int p = 0; p < 3; p++) {
        const float* W  = (p == 0) ? wq : (p == 1) ? wk : wv;
        const float* Bb = (p == 0) ? bq : (p == 1) ? bk : bv;
        float*       Op = (p == 0) ? g_rq : (p == 1) ? g_rk : g_rv;
        __syncthreads();
        for (int k = tid; k < 4096; k += 256) sw[k] = W[k];
        __syncthreads();

        unsigned long long acc[4][4];
#pragma unroll
        for (int r = 0; r < 4; r++) {
            float bi = Bb[o0 + r];
            unsigned long long bp = pack2(bi, bi);
#pragma unroll
            for (int s = 0; s < 4; s++) acc[r][s] = bp;
        }
#pragma unroll 4
        for (int c = 0; c < C_; c++) {
            unsigned long long ap[4];
#pragma unroll
            for (int r = 0; r < 4; r++) {
                float a = sw[(o0 + r)*C_ + c];
                ap[r] = pack2(a, a);
            }
            float4 b0 = *(const float4*)&sx[c*128 + tx*8];
            float4 b1 = *(const float4*)&sx[c*128 + tx*8 + 4];
            unsigned long long bv0, bv1, bv2, bv3;
            f4_to_2ull(b0, bv0, bv1);
            f4_to_2ull(b1, bv2, bv3);
#pragma unroll
            for (int r = 0; r < 4; r++) {
                fma2(acc[r][0], ap[r], bv0);
                fma2(acc[r][1], ap[r], bv1);
                fma2(acc[r][2], ap[r], bv2);
                fma2(acc[r][3], ap[r], bv3);
            }
        }
#pragma unroll
        for (int r = 0; r < 4; r++) {
            float2 u0 = unpack2(acc[r][0]), u1 = unpack2(acc[r][1]);
            float2 u2 = unpack2(acc[r][2]), u3 = unpack2(acc[r][3]);
            float4 o_0 = make_float4(fmaxf(u0.x,0.f), fmaxf(u0.y,0.f),
                                     fmaxf(u1.x,0.f), fmaxf(u1.y,0.f));
            float4 o_1 = make_float4(fmaxf(u2.x,0.f), fmaxf(u2.y,0.f),
                                     fmaxf(u3.x,0.f), fmaxf(u3.y,0.f));
            float* gp = Op + (n*C_ + o0 + r)*HW + i0 + tx*8;
            *(float4*)gp = o_0;
            *(float4*)(gp + 4) = o_1;
        }
    }
}

// ============ K2: channel score partials, grid (N_,8) x 256 ============
__global__ __launch_bounds__(256) void k_gc()
{
    int n = blockIdx.x, ic = blockIdx.y;
    int i0 = ic << 7;
    __shared__ float sq[C_*65];
    __shared__ float sk[C_*65];
    int tid = threadIdx.x, ty = tid >> 4, tx = tid & 15;

    float acc[4][4];
#pragma unroll
    for (int r = 0; r < 4; r++)
#pragma unroll
        for (int s = 0; s < 4; s++) acc[r][s] = 0.f;

    for (int it = 0; it < 2; it++) {
        __syncthreads();
        for (int k = tid; k < 4096; k += 256) {
            int c = k >> 6, ii = k & 63;
            sq[c*65 + ii] = g_rq[(n*C_ + c)*HW + i0 + it*64 + ii];
            sk[c*65 + ii] = g_rk[(n*C_ + c)*HW + i0 + it*64 + ii];
        }
        __syncthreads();
        for (int ii = 0; ii < 64; ii++) {
            float a[4], bb[4];
#pragma unroll
            for (int r = 0; r < 4; r++) a[r]  = sq[(ty*4 + r)*65 + ii];
#pragma unroll
            for (int s = 0; s < 4; s++) bb[s] = sk[(tx*4 + s)*65 + ii];
#pragma unroll
            for (int r = 0; r < 4; r++)
#pragma unroll
                for (int s = 0; s < 4; s++) acc[r][s] = fmaf(a[r], bb[s], acc[r][s]);
        }
    }
#pragma unroll
    for (int r = 0; r < 4; r++)
#pragma unroll
        for (int s = 0; s < 4; s++)
            g_gcp[(ic*N_ + n)*4096 + (ty*4 + r)*C_ + tx*4 + s] = acc[r][s];
}

// ============ K3a: reduce partials + softmax over n ============
__global__ void k_gc_softmax()
{
    int cd = blockIdx.x * 256 + threadIdx.x;   // 0..4095
    float v[N_];
    float mx = -1e30f;
#pragma unroll
    for (int n = 0; n < N_; n++) {
        float s = 0.f;
#pragma unroll
        for (int ic = 0; ic < 8; ic++) s += g_gcp[(ic*N_ + n)*4096 + cd];
        v[n] = s; mx = fmaxf(mx, s);
    }
    float s = 0.f;
#pragma unroll
    for (int n = 0; n < N_; n++) { v[n] = __expf(v[n] - mx); s += v[n]; }
    float inv = 1.f / s;
#pragma unroll
    for (int n = 0; n < N_; n++) g_gc[n*4096 + cd] = v[n] * inv;
}

// ============ K3b: a_c = m_c @ v — FMA2 GEMM, grid (N_,8) x 256 ============
// dyn smem: sv[64d][128i] + sm[64c*64d] = 48 KB
__global__ __launch_bounds__(256) void k_ac()
{
    extern __shared__ float dyn[];
    float* sv = dyn;            // 64 x 128
    float* sm = dyn + 8192;     // 64c x 64d
    int n = blockIdx.x;
    int i0 = blockIdx.y << 7;
    int tid = threadIdx.x, ty = tid >> 4, tx = tid & 15;
    int c0 = ty * 4;

    for (int k = tid; k < 2048; k += 256) {
        int d = k >> 5, f = k & 31;
        ((float4*)sv)[k] = ((const float4*)(g_rv + (n*C_ + d)*HW + i0))[f];
    }
    for (int k = tid; k < 4096; k += 256) sm[k] = g_gc[n*4096 + k];
    __syncthreads();

    unsigned long long acc[4][4];
#pragma unroll
    for (int r = 0; r < 4; r++)
#pragma unroll
        for (int s = 0; s < 4; s++) acc[r][s] = 0ULL;

#pragma unroll 4
    for (int d = 0; d < C_; d++) {
        unsigned long long ap[4];
#pragma unroll
        for (int r = 0; r < 4; r++) {
            float a = sm[(c0 + r)*C_ + d];
            ap[r] = pack2(a, a);
        }
        float4 b0 = *(const float4*)&sv[d*128 + tx*8];
        float4 b1 = *(const float4*)&sv[d*128 + tx*8 + 4];
        unsigned long long bv0, bv1, bv2, bv3;
        f4_to_2ull(b0, bv0, bv1);
        f4_to_2ull(b1, bv2, bv3);
#pragma unroll
        for (int r = 0; r < 4; r++) {
            fma2(acc[r][0], ap[r], bv0);
            fma2(acc[r][1], ap[r], bv1);
            fma2(acc[r][2], ap[r], bv2);
            fma2(acc[r][3], ap[r], bv3);
        }
    }
#pragma unroll
    for (int r = 0; r < 4; r++) {
        float2 u0 = unpack2(acc[r][0]), u1 = unpack2(acc[r][1]);
        float2 u2 = unpack2(acc[r][2]), u3 = unpack2(acc[r][3]);
        float* gp = g_s + (n*C_ + c0 + r)*HW + i0 + tx*8;
        *(float4*)gp       = make_float4(u0.x, u0.y, u1.x, u1.y);
        *(float4*)(gp + 4) = make_float4(u2.x, u2.y, u3.x, u3.y);
    }
}

// ============ K4: e = exp(q^T k) — FMA2 GEMM, grid (8,8,N_) x 256 ============
__global__ __launch_bounds__(256) void k_ms()
{
    int n  = blockIdx.z;
    int i0 = blockIdx.x << 7, j0 = blockIdx.y << 7;
    __shared__ float sq[32*128];
    __shared__ float sk[32*128];
    int tid = threadIdx.x, ty = tid >> 4, tx = tid & 15;

    unsigned long long acc[8][4];
#pragma unroll
    for (int r = 0; r < 8; r++)
#pragma unroll
        for (int s = 0; s < 4; s++) acc[r][s] = 0ULL;

    for (int cc = 0; cc < C_; cc += 32) {
        __syncthreads();
        const float* qp = g_rq + (n*C_ + cc)*HW + i0;
        const float* kp = g_rk + (n*C_ + cc)*HW + j0;
        for (int k = tid; k < 1024; k += 256) {
            int c = k >> 5, f = k & 31;
            ((float4*)sq)[k] = ((const float4*)(qp + c*HW))[f];
            ((float4*)sk)[k] = ((const float4*)(kp + c*HW))[f];
        }
        __syncthreads();
#pragma unroll 4
        for (int c = 0; c < 32; c++) {
            float4 b0 = *(const float4*)&sk[c*128 + tx*8];
            float4 b1 = *(const float4*)&sk[c*128 + tx*8 + 4];
            unsigned long long bv0, bv1, bv2, bv3;
            f4_to_2ull(b0, bv0, bv1);
            f4_to_2ull(b1, bv2, bv3);
#pragma unroll
            for (int r = 0; r < 8; r++) {
                float a = sq[c*128 + ty*8 + r];
                unsigned long long ap = pack2(a, a);
                fma2(acc[r][0], ap, bv0);
                fma2(acc[r][1], ap, bv1);
                fma2(acc[r][2], ap, bv2);
                fma2(acc[r][3], ap, bv3);
            }
        }
    }
    float* outp = g_ms + ((size_t)n << 20) + (size_t)(i0 + ty*8)*HW + j0 + tx*8;
#pragma unroll
    for (int r = 0; r < 8; r++) {
        float2 u0 = unpack2(acc[r][0]), u1 = unpack2(acc[r][1]);
        float2 u2 = unpack2(acc[r][2]), u3 = unpack2(acc[r][3]);
        float4 o0 = make_float4(__expf(u0.x), __expf(u0.y), __expf(u1.x), __expf(u1.y));
        float4 o1 = make_float4(__expf(u2.x), __expf(u2.y), __expf(u3.x), __expf(u3.y));
        *(float4*)(outp + (size_t)r*HW)     = o0;
        *(float4*)(outp + (size_t)r*HW + 4) = o1;
    }
}

// ============ K5: g_inv = 1 / sum_n e ============
__global__ __launch_bounds__(256) void k_sum()
{
    size_t ij4 = (size_t)blockIdx.x * 256 + threadIdx.x;
    const float4* base = (const float4*)g_ms;
    float4 s = make_float4(0.f, 0.f, 0.f, 0.f);
#pragma unroll
    for (int n = 0; n < N_; n++) {
        float4 v = base[((size_t)n << 18) + ij4];
        s.x += v.x; s.y += v.y; s.z += v.z; s.w += v.w;
    }
    ((float4*)g_inv)[ij4] = make_float4(1.f/s.x, 1.f/s.y, 1.f/s.z, 1.f/s.w);
}

// ============ K6: a_s = P @ v^T, g_s += — FMA2, grid (8,N_) x 256 ============
// tile: 64c x 128i, j-chunks of 32. smem sv[64][33] + seT[32][132]
__global__ __launch_bounds__(256) void k_as()
{
    int n  = blockIdx.y;
    int i0 = blockIdx.x << 7;
    __shared__ float sv[C_*33];
    __shared__ float seT[32*132];
    int tid = threadIdx.x, ty = tid >> 4, tx = tid & 15;
    int c0 = ty * 4;

    unsigned long long acc[4][4];
#pragma unroll
    for (int r = 0; r < 4; r++)
#pragma unroll
        for (int s = 0; s < 4; s++) acc[r][s] = 0ULL;

    const float* msp = g_ms + ((size_t)n << 20);
    for (int jc = 0; jc < 32; jc++) {
        int j0 = jc << 5;
        __syncthreads();
        for (int k = tid; k < 2048; k += 256) {
            int c = k >> 5, jj = k & 31;
            sv[c*33 + jj] = g_rv[(n*C_ + c)*HW + j0 + jj];
        }
        for (int k = tid; k < 4096; k += 256) {
            int ii = k >> 5, jj = k & 31;
            int gi = i0 + ii;
            seT[jj*132 + ii] = msp[(size_t)gi*HW + j0 + jj] * g_inv[gi*HW + j0 + jj];
        }
        __syncthreads();
#pragma unroll 4
        for (int j = 0; j < 32; j++) {
            unsigned long long ap[4];
#pragma unroll
            for (int r = 0; r < 4; r++) {
                float a = sv[(c0 + r)*33 + j];
                ap[r] = pack2(a, a);
            }
            float4 b0 = *(const float4*)&seT[j*132 + tx*8];
            float4 b1 = *(const float4*)&seT[j*132 + tx*8 + 4];
            unsigned long long bv0, bv1, bv2, bv3;
            f4_to_2ull(b0, bv0, bv1);
            f4_to_2ull(b1, bv2, bv3);
#pragma unroll
            for (int r = 0; r < 4; r++) {
                fma2(acc[r][0], ap[r], bv0);
                fma2(acc[r][1], ap[r], bv1);
                fma2(acc[r][2], ap[r], bv2);
                fma2(acc[r][3], ap[r], bv3);
            }
        }
    }
#pragma unroll
    for (int r = 0; r < 4; r++) {
        float2 u0 = unpack2(acc[r][0]), u1 = unpack2(acc[r][1]);
        float2 u2 = unpack2(acc[r][2]), u3 = unpack2(acc[r][3]);
        float* gp = g_s + (n*C_ + c0 + r)*HW + i0 + tx*8;
        float4 o0 = *(float4*)gp;
        float4 o1 = *(float4*)(gp + 4);
        o0.x += u0.x; o0.y += u0.y; o0.z += u1.x; o0.w += u1.y;
        o1.x += u2.x; o1.y += u2.y; o1.z += u3.x; o1.w += u3.y;
        *(float4*)gp = o0;
        *(float4*)(gp + 4) = o1;
    }
}

// ============ K7: Xe = relu(tconv3(s)) — FMA2, grid (N_,8) x 256 ============
// smem: sw[64o*64c] 16KB + ss[32c][128i] 16KB
__global__ __launch_bounds__(256) void k_tconv(const float* __restrict__ wX,
                                               const float* __restrict__ bX)
{
    __shared__ float sw[4096];
    __shared__ float ss[32*128];
    int n = blockIdx.x, b = n >> 3, t = n & 7;
    int i0 = blockIdx.y << 7;
    int tid = threadIdx.x, ty = tid >> 4, tx = tid & 15;
    int o0 = ty * 4;

    unsigned long long acc[4][4];
#pragma unroll
    for (int r = 0; r < 4; r++) {
        float bi = bX[o0 + r];
        unsigned long long bp = pack2(bi, bi);
#pragma unroll
        for (int s = 0; s < 4; s++) acc[r][s] = bp;
    }

    for (int kt = 0; kt < 3; kt++) {
        int t2 = t + kt - 1;
        if (t2 < 0 || t2 >= TT_) continue;     // block-uniform
        __syncthreads();
        for (int k = tid; k < 4096; k += 256) sw[k] = wX[k*3 + kt];
        for (int cc = 0; cc < 2; cc++) {
            __syncthreads();
            const float* sp = g_s + ((b*TT_ + t2)*C_ + cc*32)*HW + i0;
            for (int k = tid; k < 1024; k += 256) {
                int c = k >> 5, f = k & 31;
                ((float4*)ss)[k] = ((const float4*)(sp + c*HW))[f];
            }
            __syncthreads();
#pragma unroll 4
            for (int c = 0; c < 32; c++) {
                unsigned long long ap[4];
#pragma unroll
                for (int r = 0; r < 4; r++) {
                    float a = sw[(o0 + r)*C_ + cc*32 + c];
                    ap[r] = pack2(a, a);
                }
                float4 b0 = *(const float4*)&ss[c*128 + tx*8];
                float4 b1 = *(const float4*)&ss[c*128 + tx*8 + 4];
                unsigned long long bv0, bv1, bv2, bv3;
                f4_to_2ull(b0, bv0, bv1);
                f4_to_2ull(b1, bv2, bv3);
#pragma unroll
                for (int r = 0; r < 4; r++) {
                    fma2(acc[r][0], ap[r], bv0);
                    fma2(acc[r][1], ap[r], bv1);
                    fma2(acc[r][2], ap[r], bv2);
                    fma2(acc[r][3], ap[r], bv3);
                }
            }
        }
    }
#pragma unroll
    for (int r = 0; r < 4; r++) {
        float2 u0 = unpack2(acc[r][0]), u1 = unpack2(acc[r][1]);
        float2 u2 = unpack2(acc[r][2]), u3 = unpack2(acc[r][3]);
        float* gp = g_xe + (n*C_ + o0 + r)*HW + i0 + tx*8;
        *(float4*)gp       = make_float4(fmaxf(u0.x,0.f), fmaxf(u0.y,0.f),
                                         fmaxf(u1.x,0.f), fmaxf(u1.y,0.f));
        *(float4*)(gp + 4) = make_float4(fmaxf(u2.x,0.f), fmaxf(u2.y,0.f),
                                         fmaxf(u3.x,0.f), fmaxf(u3.y,0.f));
    }
}

// ============ K8a: temporal score partials, grid (B_,8) x 256 ============
__global__ __launch_bounds__(256) void k_mtp()
{
    int b = blockIdx.x, dc = blockIdx.y;
    int tid = threadIdx.x, lane = tid & 31, warp = tid >> 5;
    int d0 = dc * 8192;
    float acc[64];
#pragma unroll
    for (int a = 0; a < 64; a++) acc[a] = 0.f;

    for (int m = 0; m < 32; m++) {
        int d = d0 + m*256 + tid;
        float v[8];
#pragma unroll
        for (int t = 0; t < 8; t++) v[t] = g_xe[(size_t)(b*TT_ + t)*CHW + d];
#pragma unroll
        for (int t = 0; t < 8; t++)
#pragma unroll
            for (int s = 0; s < 8; s++) acc[t*8 + s] = fmaf(v[t], v[s], acc[t*8 + s]);
    }
#pragma unroll
    for (int a = 0; a < 64; a++) {
#pragma unroll
        for (int off = 16; off > 0; off >>= 1)
            acc[a] += __shfl_xor_sync(0xffffffffu, acc[a], off);
    }
    __shared__ float red[8][64];
    if (lane == 0)
        for (int a = 0; a < 64; a++) red[warp][a] = acc[a];
    __syncthreads();
    if (tid < 64) {
        float s = 0.f;
#pragma unroll
        for (int w = 0; w < 8; w++) s += red[w][tid];
        g_mtp[(b*8 + dc)*64 + tid] = s;
    }
}

// ============ K8b: reduce partials + softmax over b ============
__global__ void k_mt_softmax()
{
    __shared__ float sm[B_][64];
    int tid = threadIdx.x;            // 256 = 4b x 64ts
    int b = tid >> 6, ts = tid & 63;
    float s = 0.f;
#pragma unroll
    for (int dc = 0; dc < 8; dc++) s += g_mtp[(b*8 + dc)*64 + ts];
    sm[b][ts] = s;
    __syncthreads();
    if (tid < 64) {
        float v[B_];
        float mx = -1e30f;
#pragma unroll
        for (int bb = 0; bb < B_; bb++) { v[bb] = sm[bb][tid]; mx = fmaxf(mx, v[bb]); }
        float ss = 0.f;
#pragma unroll
        for (int bb = 0; bb < B_; bb++) { v[bb] = __expf(v[bb] - mx); ss += v[bb]; }
        float inv = 1.f / ss;
#pragma unroll
        for (int bb = 0; bb < B_; bb++) g_mt[bb*64 + tid] = v[bb] * inv;
    }
}

// ============ K8c: out[b,c,t,i] = sum_s m_t[b,t,s] v[b,s,c,i], grid 256 ============
__global__ __launch_bounds__(256) void k_out(float* __restrict__ out)
{
    int bc = blockIdx.x;               // b*64 + c
    int b = bc >> 6, c = bc & 63;
    __shared__ float smt[64];
    if (threadIdx.x < 64) smt[threadIdx.x] = g_mt[b*64 + threadIdx.x];
    __syncthreads();
    for (int k = 0; k < 4; k++) {
        int i = k*256 + threadIdx.x;
        float v[8];
#pragma unroll
        for (int s = 0; s < 8; s++)
            v[s] = g_rv[(size_t)((b*TT_ + s)*C_ + c)*HW + i];
#pragma unroll
        for (int t = 0; t < 8; t++) {
            float a = 0.f;
#pragma unroll
            for (int s = 0; s < 8; s++) a = fmaf(smt[t*8 + s], v[s], a);
            out[(size_t)((b*C_ + c)*TT_ + t)*HW + i] = a;
        }
    }
}

// ---------------- launch ----------------
extern "C" void kernel_launch(void* const* d_in, const int* in_sizes, int n_in,
                              void* d_out, int out_size)
{
    const float* x  = (const float*)d_in[0];
    const float* wq = (const float*)d_in[1];
    const float* bq = (const float*)d_in[2];
    const float* wk = (const float*)d_in[3];
    const float* bk = (const float*)d_in[4];
    const float* wv = (const float*)d_in[5];
    const float* bv = (const float*)d_in[6];
    const float* wX = (const float*)d_in[7];
    const float* bX = (const float*)d_in[8];
    float* out = (float*)d_out;
    (void)in_sizes; (void)n_in; (void)out_size;

    static bool attr_done = false;
    if (!attr_done) {
        cudaFuncSetAttribute(k_qkv, cudaFuncAttributeMaxDynamicSharedMemorySize, 49152);
        cudaFuncSetAttribute(k_ac,  cudaFuncAttributeMaxDynamicSharedMemorySize, 49152);
        attr_done = true;
    }

    k_qkv<<<dim3(N_, 8), 256, 49152>>>(x, wq, bq, wk, bk, wv, bv);
    k_gc<<<dim3(N_, 8), 256>>>();
    k_gc_softmax<<<16, 256>>>();
    k_ac<<<dim3(N_, 8), 256, 49152>>>();
    k_ms<<<dim3(8, 8, N_), 256>>>();
    k_sum<<<1024, 256>>>();
    k_as<<<dim3(8, N_), 256>>>();
    k_tconv<<<dim3(N_, 8), 256>>>(wX, bX);
    k_mtp<<<dim3(B_, 8), 256>>>();
    k_mt_softmax<<<1, 256>>>();
    k_out<<<256, 256>>>(out);
}

// round 5
// speedup vs baseline: 1.2714x; 1.0245x over previous
#include <cuda_runtime.h>

// Problem constants: B=4, C=64, T=8, H=32, W=32, O=64
#define B_   4
#define TT_  8
#define N_   32          // B*T
#define C_   64
#define HW   1024        // H*W
#define CHW  65536       // C*HW

typedef unsigned long long ull;

// ---------------- f32x2 helpers ----------------
__device__ __forceinline__ ull pack2(float a, float b) {
    ull r;
    asm("mov.b64 %0,{%1,%2};" : "=l"(r) : "f"(a), "f"(b));
    return r;
}
__device__ __forceinline__ void fma2(ull& d, ull a, ull b) {
    asm("fma.rn.f32x2 %0,%1,%2,%0;" : "+l"(d) : "l"(a), "l"(b));
}
__device__ __forceinline__ float2 unpack2(ull v) {
    float2 f;
    asm("mov.b64 {%0,%1},%2;" : "=f"(f.x), "=f"(f.y) : "l"(v));
    return f;
}
__device__ __forceinline__ void f4_to_2ull(float4 v, ull& lo, ull& hi) {
    lo = pack2(v.x, v.y);
    hi = pack2(v.z, v.w);
}
// vector load of two packed f32 pairs from shared (16B aligned)
__device__ __forceinline__ void lds2(ull& a, ull& b, unsigned sa) {
    asm volatile("ld.shared.v2.u64 {%0,%1},[%2];" : "=l"(a), "=l"(b) : "r"(sa));
}

// ---------------- scratch (device globals; no allocation) ----------------
__device__ float g_rq[N_*C_*HW];               // 8 MB
__device__ float g_rk[N_*C_*HW];               // 8 MB
__device__ float g_rv[N_*C_*HW];               // 8 MB
__device__ float g_gcp[8*N_*C_*C_];            // 4 MB channel-score i-partials
__device__ float g_gc[N_*C_*C_];               // 512 KB softmaxed channel attn
__device__ float g_ms[(size_t)N_*HW*HW];       // 128 MB exp(spatial scores)
__device__ float g_inv[HW*HW];                 // 4 MB 1/sum_n exp
__device__ float g_s [N_*C_*HW];               // 8 MB a_c + a_s(half 0)
__device__ float g_sp[N_*C_*HW];               // 8 MB a_s(half 1) partial
__device__ float g_xe[N_*C_*HW];               // 8 MB relu(tconv3)
__device__ float g_mtp[B_*8*64];               // temporal score partials
__device__ float g_mt[B_*TT_*TT_];             // temporal softmax

// ============ K1: one projection per z: relu(W x + b), grid (N_,8,3) ============
__global__ __launch_bounds__(256) void k_qkv(
    const float* __restrict__ x,
    const float* __restrict__ wq, const float* __restrict__ bq,
    const float* __restrict__ wk, const float* __restrict__ bk,
    const float* __restrict__ wv, const float* __restrict__ bv)
{
    extern __shared__ float dyn[];
    float* sx = dyn;            // 64 x 128
    float* sw = dyn + 8192;     // 64o x 64c
    int n = blockIdx.x, b = n >> 3, t = n & 7;
    int i0 = blockIdx.y << 7;
    int p = blockIdx.z;
    int tid = threadIdx.x, ty = tid >> 4, tx = tid & 15;
    int o0 = ty * 4;

    const float* W  = (p == 0) ? wq : (p == 1) ? wk : wv;
    const float* Bb = (p == 0) ? bq : (p == 1) ? bk : bv;
    float*       Op = (p == 0) ? g_rq : (p == 1) ? g_rk : g_rv;

    for (int k = tid; k < 2048; k += 256) {
        int c = k >> 5, f = k & 31;
        ((float4*)sx)[k] =
            ((const float4*)(x + ((size_t)(b*C_ + c)*TT_ + t)*HW + i0))[f];
    }
    for (int k = tid; k < 4096; k += 256) sw[k] = W[k];
    __syncthreads();

    ull acc[4][4];
#pragma unroll
    for (int r = 0; r < 4; r++) {
        float bi = Bb[o0 + r];
        ull bp = pack2(bi, bi);
#pragma unroll
        for (int s = 0; s < 4; s++) acc[r][s] = bp;
    }
#pragma unroll 4
    for (int c = 0; c < C_; c++) {
        ull ap[4];
#pragma unroll
        for (int r = 0; r < 4; r++) {
            float a = sw[(o0 + r)*C_ + c];
            ap[r] = pack2(a, a);
        }
        float4 b0 = *(const float4*)&sx[c*128 + tx*8];
        float4 b1 = *(const float4*)&sx[c*128 + tx*8 + 4];
        ull bv0, bv1, bv2, bv3;
        f4_to_2ull(b0, bv0, bv1);
        f4_to_2ull(b1, bv2, bv3);
#pragma unroll
        for (int r = 0; r < 4; r++) {
            fma2(acc[r][0], ap[r], bv0);
            fma2(acc[r][1], ap[r], bv1);
            fma2(acc[r][2], ap[r], bv2);
            fma2(acc[r][3], ap[r], bv3);
        }
    }
#pragma unroll
    for (int r = 0; r < 4; r++) {
        float2 u0 = unpack2(acc[r][0]), u1 = unpack2(acc[r][1]);
        float2 u2 = unpack2(acc[r][2]), u3 = unpack2(acc[r][3]);
        float* gp = Op + (n*C_ + o0 + r)*HW + i0 + tx*8;
        *(float4*)gp       = make_float4(fmaxf(u0.x,0.f), fmaxf(u0.y,0.f),
                                         fmaxf(u1.x,0.f), fmaxf(u1.y,0.f));
        *(float4*)(gp + 4) = make_float4(fmaxf(u2.x,0.f), fmaxf(u2.y,0.f),
                                         fmaxf(u3.x,0.f), fmaxf(u3.y,0.f));
    }
}

// ============ K2: channel score partials, grid (N_,8) x 256 ============
__global__ __launch_bounds__(256) void k_gc()
{
    int n = blockIdx.x, ic = blockIdx.y;
    int i0 = ic << 7;
    __shared__ float sq[C_*65];
    __shared__ float sk[C_*65];
    int tid = threadIdx.x, ty = tid >> 4, tx = tid & 15;

    float acc[4][4];
#pragma unroll
    for (int r = 0; r < 4; r++)
#pragma unroll
        for (int s = 0; s < 4; s++) acc[r][s] = 0.f;

    for (int it = 0; it < 2; it++) {
        __syncthreads();
        for (int k = tid; k < 4096; k += 256) {
            int c = k >> 6, ii = k & 63;
            sq[c*65 + ii] = g_rq[(n*C_ + c)*HW + i0 + it*64 + ii];
            sk[c*65 + ii] = g_rk[(n*C_ + c)*HW + i0 + it*64 + ii];
        }
        __syncthreads();
        for (int ii = 0; ii < 64; ii++) {
            float a[4], bb[4];
#pragma unroll
            for (int r = 0; r < 4; r++) a[r]  = sq[(ty*4 + r)*65 + ii];
#pragma unroll
            for (int s = 0; s < 4; s++) bb[s] = sk[(tx*4 + s)*65 + ii];
#pragma unroll
            for (int r = 0; r < 4; r++)
#pragma unroll
                for (int s = 0; s < 4; s++) acc[r][s] = fmaf(a[r], bb[s], acc[r][s]);
        }
    }
#pragma unroll
    for (int r = 0; r < 4; r++)
#pragma unroll
        for (int s = 0; s < 4; s++)
            g_gcp[(ic*N_ + n)*4096 + (ty*4 + r)*C_ + tx*4 + s] = acc[r][s];
}

// ============ K3a: reduce partials + softmax over n ============
__global__ void k_gc_softmax()
{
    int cd = blockIdx.x * 256 + threadIdx.x;
    float v[N_];
    float mx = -1e30f;
#pragma unroll
    for (int n = 0; n < N_; n++) {
        float s = 0.f;
#pragma unroll
        for (int ic = 0; ic < 8; ic++) s += g_gcp[(ic*N_ + n)*4096 + cd];
        v[n] = s; mx = fmaxf(mx, s);
    }
    float s = 0.f;
#pragma unroll
    for (int n = 0; n < N_; n++) { v[n] = __expf(v[n] - mx); s += v[n]; }
    float inv = 1.f / s;
#pragma unroll
    for (int n = 0; n < N_; n++) g_gc[n*4096 + cd] = v[n] * inv;
}

// ============ K3b: a_c = m_c @ v — FMA2 GEMM, grid (N_,8) ============
__global__ __launch_bounds__(256) void k_ac()
{
    extern __shared__ float dyn[];
    float* sv = dyn;            // 64 x 128
    float* sm = dyn + 8192;     // 64c x 64d
    int n = blockIdx.x;
    int i0 = blockIdx.y << 7;
    int tid = threadIdx.x, ty = tid >> 4, tx = tid & 15;
    int c0 = ty * 4;

    for (int k = tid; k < 2048; k += 256) {
        int d = k >> 5, f = k & 31;
        ((float4*)sv)[k] = ((const float4*)(g_rv + (n*C_ + d)*HW + i0))[f];
    }
    for (int k = tid; k < 4096; k += 256) sm[k] = g_gc[n*4096 + k];
    __syncthreads();

    ull acc[4][4];
#pragma unroll
    for (int r = 0; r < 4; r++)
#pragma unroll
        for (int s = 0; s < 4; s++) acc[r][s] = 0ULL;

#pragma unroll 4
    for (int d = 0; d < C_; d++) {
        ull ap[4];
#pragma unroll
        for (int r = 0; r < 4; r++) {
            float a = sm[(c0 + r)*C_ + d];
            ap[r] = pack2(a, a);
        }
        float4 b0 = *(const float4*)&sv[d*128 + tx*8];
        float4 b1 = *(const float4*)&sv[d*128 + tx*8 + 4];
        ull bv0, bv1, bv2, bv3;
        f4_to_2ull(b0, bv0, bv1);
        f4_to_2ull(b1, bv2, bv3);
#pragma unroll
        for (int r = 0; r < 4; r++) {
            fma2(acc[r][0], ap[r], bv0);
            fma2(acc[r][1], ap[r], bv1);
            fma2(acc[r][2], ap[r], bv2);
            fma2(acc[r][3], ap[r], bv3);
        }
    }
#pragma unroll
    for (int r = 0; r < 4; r++) {
        float2 u0 = unpack2(acc[r][0]), u1 = unpack2(acc[r][1]);
        float2 u2 = unpack2(acc[r][2]), u3 = unpack2(acc[r][3]);
        float* gp = g_s + (n*C_ + c0 + r)*HW + i0 + tx*8;
        *(float4*)gp       = make_float4(u0.x, u0.y, u1.x, u1.y);
        *(float4*)(gp + 4) = make_float4(u2.x, u2.y, u3.x, u3.y);
    }
}

// ============ K4: e = exp(q^T k) — dup-q FMA2 GEMM, grid (8,8,N_) ============
// smem: sqd 32c x 256 (q duplicated pairs) 32KB + sk 32c x 128 16KB = 48KB
__global__ __launch_bounds__(256, 2) void k_ms()
{
    __shared__ float sqd[32*256];
    __shared__ float sk[32*128];
    int n  = blockIdx.z;
    int i0 = blockIdx.x << 7, j0 = blockIdx.y << 7;
    int tid = threadIdx.x, ty = tid >> 4, tx = tid & 15;
    unsigned sq_base = (unsigned)__cvta_generic_to_shared(sqd) + ty*64;  // ty*16 floats
    unsigned sk_base = (unsigned)__cvta_generic_to_shared(sk)  + tx*32;  // tx*8 floats

    ull acc[8][4];
#pragma unroll
    for (int r = 0; r < 8; r++)
#pragma unroll
        for (int s = 0; s < 4; s++) acc[r][s] = 0ULL;

    for (int cc = 0; cc < C_; cc += 32) {
        __syncthreads();
        const float* qp = g_rq + (n*C_ + cc)*HW + i0;
        const float* kp = g_rk + (n*C_ + cc)*HW + j0;
        for (int k = tid; k < 1024; k += 256) {
            int c = k >> 5, f = k & 31;
            ((float4*)sk)[k] = ((const float4*)(kp + c*HW))[f];
            float4 q4 = ((const float4*)(qp + c*HW))[f];
            ((float4*)sqd)[c*64 + 2*f]     = make_float4(q4.x, q4.x, q4.y, q4.y);
            ((float4*)sqd)[c*64 + 2*f + 1] = make_float4(q4.z, q4.z, q4.w, q4.w);
        }
        __syncthreads();
#pragma unroll 8
        for (int c = 0; c < 32; c++) {
            ull b0, b1, b2, b3;
            lds2(b0, b1, sk_base + c*512);
            lds2(b2, b3, sk_base + c*512 + 16);
            ull a0, a1, a2, a3, a4, a5, a6, a7;
            lds2(a0, a1, sq_base + c*1024);
            lds2(a2, a3, sq_base + c*1024 + 16);
            lds2(a4, a5, sq_base + c*1024 + 32);
            lds2(a6, a7, sq_base + c*1024 + 48);
            fma2(acc[0][0],a0,b0); fma2(acc[0][1],a0,b1); fma2(acc[0][2],a0,b2); fma2(acc[0][3],a0,b3);
            fma2(acc[1][0],a1,b0); fma2(acc[1][1],a1,b1); fma2(acc[1][2],a1,b2); fma2(acc[1][3],a1,b3);
            fma2(acc[2][0],a2,b0); fma2(acc[2][1],a2,b1); fma2(acc[2][2],a2,b2); fma2(acc[2][3],a2,b3);
            fma2(acc[3][0],a3,b0); fma2(acc[3][1],a3,b1); fma2(acc[3][2],a3,b2); fma2(acc[3][3],a3,b3);
            fma2(acc[4][0],a4,b0); fma2(acc[4][1],a4,b1); fma2(acc[4][2],a4,b2); fma2(acc[4][3],a4,b3);
            fma2(acc[5][0],a5,b0); fma2(acc[5][1],a5,b1); fma2(acc[5][2],a5,b2); fma2(acc[5][3],a5,b3);
            fma2(acc[6][0],a6,b0); fma2(acc[6][1],a6,b1); fma2(acc[6][2],a6,b2); fma2(acc[6][3],a6,b3);
            fma2(acc[7][0],a7,b0); fma2(acc[7][1],a7,b1); fma2(acc[7][2],a7,b2); fma2(acc[7][3],a7,b3);
        }
    }
    float* outp = g_ms + ((size_t)n << 20) + (size_t)(i0 + ty*8)*HW + j0 + tx*8;
#pragma unroll
    for (int r = 0; r < 8; r++) {
        float2 u0 = unpack2(acc[r][0]), u1 = unpack2(acc[r][1]);
        float2 u2 = unpack2(acc[r][2]), u3 = unpack2(acc[r][3]);
        *(float4*)(outp + (size_t)r*HW)     =
            make_float4(__expf(u0.x), __expf(u0.y), __expf(u1.x), __expf(u1.y));
        *(float4*)(outp + (size_t)r*HW + 4) =
            make_float4(__expf(u2.x), __expf(u2.y), __expf(u3.x), __expf(u3.y));
    }
}

// ============ K5: g_inv = 1 / sum_n e ============
__global__ __launch_bounds__(256) void k_sum()
{
    size_t ij4 = (size_t)blockIdx.x * 256 + threadIdx.x;
    const float4* base = (const float4*)g_ms;
    float4 s = make_float4(0.f, 0.f, 0.f, 0.f);
#pragma unroll
    for (int n = 0; n < N_; n++) {
        float4 v = base[((size_t)n << 18) + ij4];
        s.x += v.x; s.y += v.y; s.z += v.z; s.w += v.w;
    }
    ((float4*)g_inv)[ij4] = make_float4(1.f/s.x, 1.f/s.y, 1.f/s.z, 1.f/s.w);
}

// ============ K6: a_s = P @ v^T — FMA2, grid (8 i-tiles, 2 j-halves, N_) ============
// jh=0 accumulates into g_s (holds a_c); jh=1 writes g_sp partial.
__global__ __launch_bounds__(256, 2) void k_as()
{
    int n  = blockIdx.z;
    int jh = blockIdx.y;
    int i0 = blockIdx.x << 7;
    __shared__ float sv [C_*33];    // [c][jj] pad 33
    __shared__ float seT[32*132];   // [jj][ii] P^T, pad 132 (16B-aligned rows)
    int tid = threadIdx.x, ty = tid >> 4, tx = tid & 15;
    int c0 = ty * 4;
    unsigned se_base = (unsigned)__cvta_generic_to_shared(seT) + tx*32;

    ull acc[4][4];
#pragma unroll
    for (int r = 0; r < 4; r++)
#pragma unroll
        for (int s = 0; s < 4; s++) acc[r][s] = 0ULL;

    const float* msp = g_ms + ((size_t)n << 20);
    for (int jc = 0; jc < 16; jc++) {
        int j0 = jh*512 + jc*32;
        __syncthreads();
        for (int k = tid; k < 2048; k += 256) {
            int c = k >> 5, jj = k & 31;
            sv[c*33 + jj] = g_rv[(n*C_ + c)*HW + j0 + jj];
        }
        for (int k = tid; k < 4096; k += 256) {
            int ii = k >> 5, jj = k & 31;
            int gi = i0 + ii;
            seT[jj*132 + ii] = msp[(size_t)gi*HW + j0 + jj] * g_inv[gi*HW + j0 + jj];
        }
        __syncthreads();
#pragma unroll 8
        for (int j = 0; j < 32; j++) {
            ull ap[4];
#pragma unroll
            for (int r = 0; r < 4; r++) {
                float a = sv[(c0 + r)*33 + j];
                ap[r] = pack2(a, a);
            }
            ull b0, b1, b2, b3;
            lds2(b0, b1, se_base + j*528);
            lds2(b2, b3, se_base + j*528 + 16);
#pragma unroll
            for (int r = 0; r < 4; r++) {
                fma2(acc[r][0], ap[r], b0);
                fma2(acc[r][1], ap[r], b1);
                fma2(acc[r][2], ap[r], b2);
                fma2(acc[r][3], ap[r], b3);
            }
        }
    }
    if (jh == 0) {
#pragma unroll
        for (int r = 0; r < 4; r++) {
            float2 u0 = unpack2(acc[r][0]), u1 = unpack2(acc[r][1]);
            float2 u2 = unpack2(acc[r][2]), u3 = unpack2(acc[r][3]);
            float* gp = g_s + (n*C_ + c0 + r)*HW + i0 + tx*8;
            float4 o0 = *(float4*)gp;
            float4 o1 = *(float4*)(gp + 4);
            o0.x += u0.x; o0.y += u0.y; o0.z += u1.x; o0.w += u1.y;
            o1.x += u2.x; o1.y += u2.y; o1.z += u3.x; o1.w += u3.y;
            *(float4*)gp = o0;
            *(float4*)(gp + 4) = o1;
        }
    } else {
#pragma unroll
        for (int r = 0; r < 4; r++) {
            float2 u0 = unpack2(acc[r][0]), u1 = unpack2(acc[r][1]);
            float2 u2 = unpack2(acc[r][2]), u3 = unpack2(acc[r][3]);
            float* gp = g_sp + (n*C_ + c0 + r)*HW + i0 + tx*8;
            *(float4*)gp       = make_float4(u0.x, u0.y, u1.x, u1.y);
            *(float4*)(gp + 4) = make_float4(u2.x, u2.y, u3.x, u3.y);
        }
    }
}

// ============ K7: Xe = relu(tconv3(g_s + g_sp)) — FMA2, grid (N_,8) ============
__global__ __launch_bounds__(256) void k_tconv(const float* __restrict__ wX,
                                               const float* __restrict__ bX)
{
    __shared__ float sw[4096];
    __shared__ float ss[32*128];
    int n = blockIdx.x, b = n >> 3, t = n & 7;
    int i0 = blockIdx.y << 7;
    int tid = threadIdx.x, ty = tid >> 4, tx = tid & 15;
    int o0 = ty * 4;

    ull acc[4][4];
#pragma unroll
    for (int r = 0; r < 4; r++) {
        float bi = bX[o0 + r];
        ull bp = pack2(bi, bi);
#pragma unroll
        for (int s = 0; s < 4; s++) acc[r][s] = bp;
    }

    for (int kt = 0; kt < 3; kt++) {
        int t2 = t + kt - 1;
        if (t2 < 0 || t2 >= TT_) continue;     // block-uniform
        __syncthreads();
        for (int k = tid; k < 4096; k += 256) sw[k] = wX[k*3 + kt];
        for (int cc = 0; cc < 2; cc++) {
            __syncthreads();
            size_t off = (size_t)((b*TT_ + t2)*C_ + cc*32)*HW + i0;
            for (int k = tid; k < 1024; k += 256) {
                int c = k >> 5, f = k & 31;
                float4 v0 = ((const float4*)(g_s  + off + c*HW))[f];
                float4 v1 = ((const float4*)(g_sp + off + c*HW))[f];
                ((float4*)ss)[k] = make_float4(v0.x+v1.x, v0.y+v1.y, v0.z+v1.z, v0.w+v1.w);
            }
            __syncthreads();
#pragma unroll 4
            for (int c = 0; c < 32; c++) {
                ull ap[4];
#pragma unroll
                for (int r = 0; r < 4; r++) {
                    float a = sw[(o0 + r)*C_ + cc*32 + c];
                    ap[r] = pack2(a, a);
                }
                float4 b0 = *(const float4*)&ss[c*128 + tx*8];
                float4 b1 = *(const float4*)&ss[c*128 + tx*8 + 4];
                ull bv0, bv1, bv2, bv3;
                f4_to_2ull(b0, bv0, bv1);
                f4_to_2ull(b1, bv2, bv3);
#pragma unroll
                for (int r = 0; r < 4; r++) {
                    fma2(acc[r][0], ap[r], bv0);
                    fma2(acc[r][1], ap[r], bv1);
                    fma2(acc[r][2], ap[r], bv2);
                    fma2(acc[r][3], ap[r], bv3);
                }
            }
        }
    }
#pragma unroll
    for (int r = 0; r < 4; r++) {
        float2 u0 = unpack2(acc[r][0]), u1 = unpack2(acc[r][1]);
        float2 u2 = unpack2(acc[r][2]), u3 = unpack2(acc[r][3]);
        float* gp = g_xe + (n*C_ + o0 + r)*HW + i0 + tx*8;
        *(float4*)gp       = make_float4(fmaxf(u0.x,0.f), fmaxf(u0.y,0.f),
                                         fmaxf(u1.x,0.f), fmaxf(u1.y,0.f));
        *(float4*)(gp + 4) = make_float4(fmaxf(u2.x,0.f), fmaxf(u2.y,0.f),
                                         fmaxf(u3.x,0.f), fmaxf(u3.y,0.f));
    }
}

// ============ K8a: temporal score partials, grid (B_,8) ============
__global__ __launch_bounds__(256) void k_mtp()
{
    int b = blockIdx.x, dc = blockIdx.y;
    int tid = threadIdx.x, lane = tid & 31, warp = tid >> 5;
    int d0 = dc * 8192;
    float acc[64];
#pragma unroll
    for (int a = 0; a < 64; a++) acc[a] = 0.f;

    for (int m = 0; m < 32; m++) {
        int d = d0 + m*256 + tid;
        float v[8];
#pragma unroll
        for (int t = 0; t < 8; t++) v[t] = g_xe[(size_t)(b*TT_ + t)*CHW + d];
#pragma unroll
        for (int t = 0; t < 8; t++)
#pragma unroll
            for (int s = 0; s < 8; s++) acc[t*8 + s] = fmaf(v[t], v[s], acc[t*8 + s]);
    }
#pragma unroll
    for (int a = 0; a < 64; a++) {
#pragma unroll
        for (int off = 16; off > 0; off >>= 1)
            acc[a] += __shfl_xor_sync(0xffffffffu, acc[a], off);
    }
    __shared__ float red[8][64];
    if (lane == 0)
        for (int a = 0; a < 64; a++) red[warp][a] = acc[a];
    __syncthreads();
    if (tid < 64) {
        float s = 0.f;
#pragma unroll
        for (int w = 0; w < 8; w++) s += red[w][tid];
        g_mtp[(b*8 + dc)*64 + tid] = s;
    }
}

// ============ K8b: reduce partials + softmax over b ============
__global__ void k_mt_softmax()
{
    __shared__ float sm[B_][64];
    int tid = threadIdx.x;
    int b = tid >> 6, ts = tid & 63;
    float s = 0.f;
#pragma unroll
    for (int dc = 0; dc < 8; dc++) s += g_mtp[(b*8 + dc)*64 + ts];
    sm[b][ts] = s;
    __syncthreads();
    if (tid < 64) {
        float v[B_];
        float mx = -1e30f;
#pragma unroll
        for (int bb = 0; bb < B_; bb++) { v[bb] = sm[bb][tid]; mx = fmaxf(mx, v[bb]); }
        float ss = 0.f;
#pragma unroll
        for (int bb = 0; bb < B_; bb++) { v[bb] = __expf(v[bb] - mx); ss += v[bb]; }
        float inv = 1.f / ss;
#pragma unroll
        for (int bb = 0; bb < B_; bb++) g_mt[bb*64 + tid] = v[bb] * inv;
    }
}

// ============ K8c: out[b,c,t,i] = sum_s m_t[b,t,s] v[b,s,c,i], grid 256 ============
__global__ __launch_bounds__(256) void k_out(float* __restrict__ out)
{
    int bc = blockIdx.x;
    int b = bc >> 6, c = bc & 63;
    __shared__ float smt[64];
    if (threadIdx.x < 64) smt[threadIdx.x] = g_mt[b*64 + threadIdx.x];
    __syncthreads();
    for (int k = 0; k < 4; k++) {
        int i = k*256 + threadIdx.x;
        float v[8];
#pragma unroll
        for (int s = 0; s < 8; s++)
            v[s] = g_rv[(size_t)((b*TT_ + s)*C_ + c)*HW + i];
#pragma unroll
        for (int t = 0; t < 8; t++) {
            float a = 0.f;
#pragma unroll
            for (int s = 0; s < 8; s++) a = fmaf(smt[t*8 + s], v[s], a);
            out[(size_t)((b*C_ + c)*TT_ + t)*HW + i] = a;
        }
    }
}

// ---------------- launch ----------------
extern "C" void kernel_launch(void* const* d_in, const int* in_sizes, int n_in,
                              void* d_out, int out_size)
{
    const float* x  = (const float*)d_in[0];
    const float* wq = (const float*)d_in[1];
    const float* bq = (const float*)d_in[2];
    const float* wk = (const float*)d_in[3];
    const float* bk = (const float*)d_in[4];
    const float* wv = (const float*)d_in[5];
    const float* bv = (const float*)d_in[6];
    const float* wX = (const float*)d_in[7];
    const float* bX = (const float*)d_in[8];
    float* out = (float*)d_out;
    (void)in_sizes; (void)n_in; (void)out_size;

    // idempotent, deterministic (same calls every invocation)
    cudaFuncSetAttribute(k_qkv, cudaFuncAttributeMaxDynamicSharedMemorySize, 49152);
    cudaFuncSetAttribute(k_ac,  cudaFuncAttributeMaxDynamicSharedMemorySize, 49152);

    k_qkv<<<dim3(N_, 8, 3), 256, 49152>>>(x, wq, bq, wk, bk, wv, bv);
    k_gc<<<dim3(N_, 8), 256>>>();
    k_gc_softmax<<<16, 256>>>();
    k_ac<<<dim3(N_, 8), 256, 49152>>>();
    k_ms<<<dim3(8, 8, N_), 256>>>();
    k_sum<<<1024, 256>>>();
    k_as<<<dim3(8, 2, N_), 256>>>();
    k_tconv<<<dim3(N_, 8), 256>>>(wX, bX);
    k_mtp<<<dim3(B_, 8), 256>>>();
    k_mt_softmax<<<1, 256>>>();
    k_out<<<256, 256>>>(out);
}

// round 7
// speedup vs baseline: 1.3837x; 1.0884x over previous
#include <cuda_runtime.h>
#include <cuda_fp16.h>

// Problem constants: B=4, C=64, T=8, H=32, W=32, O=64
#define B_   4
#define TT_  8
#define N_   32          // B*T
#define C_   64
#define HW   1024        // H*W
#define CHW  65536       // C*HW

typedef unsigned long long ull;

// ---------------- f32x2 helpers ----------------
__device__ __forceinline__ ull pack2(float a, float b) {
    ull r;
    asm("mov.b64 %0,{%1,%2};" : "=l"(r) : "f"(a), "f"(b));
    return r;
}
__device__ __forceinline__ void fma2(ull& d, ull a, ull b) {
    asm("fma.rn.f32x2 %0,%1,%2,%0;" : "+l"(d) : "l"(a), "l"(b));
}
__device__ __forceinline__ float2 unpack2(ull v) {
    float2 f;
    asm("mov.b64 {%0,%1},%2;" : "=f"(f.x), "=f"(f.y) : "l"(v));
    return f;
}
__device__ __forceinline__ void f4_to_2ull(float4 v, ull& lo, ull& hi) {
    lo = pack2(v.x, v.y);
    hi = pack2(v.z, v.w);
}
__device__ __forceinline__ void lds2(ull& a, ull& b, unsigned sa) {
    asm volatile("ld.shared.v2.u64 {%0,%1},[%2];" : "=l"(a), "=l"(b) : "r"(sa));
}

// ---------------- scratch (device globals; no allocation) ----------------
__device__ float  g_rq[N_*C_*HW];               // 8 MB
__device__ float  g_rk[N_*C_*HW];               // 8 MB
__device__ float  g_rv[N_*C_*HW];               // 8 MB
__device__ float  g_gcp[16*N_*C_*C_];           // 8 MB channel-score i-partials
__device__ float  g_gc[N_*C_*C_];               // 512 KB softmaxed channel attn
__device__ __half g_ms[(size_t)N_*HW*HW];       // 64 MB exp(spatial scores), fp16
__device__ float  g_inv[HW*HW];                 // 4 MB 1/sum_n exp
__device__ float  g_s [N_*C_*HW];               // 8 MB a_c + a_s(half 0)
__device__ float  g_sp[N_*C_*HW];               // 8 MB a_s(half 1) partial
__device__ float  g_xe[N_*C_*HW];               // 8 MB relu(tconv3)
__device__ float  g_mtp[B_*8*64];               // temporal score partials
__device__ float  g_mt[B_*TT_*TT_];             // temporal softmax

// ============ K1: one projection per z: relu(W x + b), grid (N_,8,3) ============
__global__ __launch_bounds__(256) void k_qkv(
    const float* __restrict__ x,
    const float* __restrict__ wq, const float* __restrict__ bq,
    const float* __restrict__ wk, const float* __restrict__ bk,
    const float* __restrict__ wv, const float* __restrict__ bv)
{
    extern __shared__ float dyn[];
    float* sx = dyn;            // 64 x 128
    float* sw = dyn + 8192;     // 64o x 64c
    int n = blockIdx.x, b = n >> 3, t = n & 7;
    int i0 = blockIdx.y << 7;
    int p = blockIdx.z;
    int tid = threadIdx.x, ty = tid >> 4, tx = tid & 15;
    int o0 = ty * 4;

    const float* W  = (p == 0) ? wq : (p == 1) ? wk : wv;
    const float* Bb = (p == 0) ? bq : (p == 1) ? bk : bv;
    float*       Op = (p == 0) ? g_rq : (p == 1) ? g_rk : g_rv;

    for (int k = tid; k < 2048; k += 256) {
        int c = k >> 5, f = k & 31;
        ((float4*)sx)[k] =
            ((const float4*)(x + ((size_t)(b*C_ + c)*TT_ + t)*HW + i0))[f];
    }
    for (int k = tid; k < 4096; k += 256) sw[k] = W[k];
    __syncthreads();

    ull acc[4][4];
#pragma unroll
    for (int r = 0; r < 4; r++) {
        float bi = Bb[o0 + r];
        ull bp = pack2(bi, bi);
#pragma unroll
        for (int s = 0; s < 4; s++) acc[r][s] = bp;
    }
#pragma unroll 4
    for (int c = 0; c < C_; c++) {
        ull ap[4];
#pragma unroll
        for (int r = 0; r < 4; r++) {
            float a = sw[(o0 + r)*C_ + c];
            ap[r] = pack2(a, a);
        }
        float4 b0 = *(const float4*)&sx[c*128 + tx*8];
        float4 b1 = *(const float4*)&sx[c*128 + tx*8 + 4];
        ull bv0, bv1, bv2, bv3;
        f4_to_2ull(b0, bv0, bv1);
        f4_to_2ull(b1, bv2, bv3);
#pragma unroll
        for (int r = 0; r < 4; r++) {
            fma2(acc[r][0], ap[r], bv0);
            fma2(acc[r][1], ap[r], bv1);
            fma2(acc[r][2], ap[r], bv2);
            fma2(acc[r][3], ap[r], bv3);
        }
    }
#pragma unroll
    for (int r = 0; r < 4; r++) {
        float2 u0 = unpack2(acc[r][0]), u1 = unpack2(acc[r][1]);
        float2 u2 = unpack2(acc[r][2]), u3 = unpack2(acc[r][3]);
        float* gp = Op + (n*C_ + o0 + r)*HW + i0 + tx*8;
        *(float4*)gp       = make_float4(fmaxf(u0.x,0.f), fmaxf(u0.y,0.f),
                                         fmaxf(u1.x,0.f), fmaxf(u1.y,0.f));
        *(float4*)(gp + 4) = make_float4(fmaxf(u2.x,0.f), fmaxf(u2.y,0.f),
                                         fmaxf(u3.x,0.f), fmaxf(u3.y,0.f));
    }
}

// ============ K2: channel score partials, grid (N_,16) x 256 ============
__global__ __launch_bounds__(256) void k_gc()
{
    int n = blockIdx.x, ic = blockIdx.y;   // 16 i-chunks of 64
    int i0 = ic << 6;
    __shared__ float sq[C_*65];
    __shared__ float sk[C_*65];
    int tid = threadIdx.x, ty = tid >> 4, tx = tid & 15;

    for (int k = tid; k < 4096; k += 256) {
        int c = k >> 6, ii = k & 63;
        sq[c*65 + ii] = g_rq[(n*C_ + c)*HW + i0 + ii];
        sk[c*65 + ii] = g_rk[(n*C_ + c)*HW + i0 + ii];
    }
    __syncthreads();

    float acc[4][4];
#pragma unroll
    for (int r = 0; r < 4; r++)
#pragma unroll
        for (int s = 0; s < 4; s++) acc[r][s] = 0.f;

    for (int ii = 0; ii < 64; ii++) {
        float a[4], bb[4];
#pragma unroll
        for (int r = 0; r < 4; r++) a[r]  = sq[(ty*4 + r)*65 + ii];
#pragma unroll
        for (int s = 0; s < 4; s++) bb[s] = sk[(tx*4 + s)*65 + ii];
#pragma unroll
        for (int r = 0; r < 4; r++)
#pragma unroll
            for (int s = 0; s < 4; s++) acc[r][s] = fmaf(a[r], bb[s], acc[r][s]);
    }
#pragma unroll
    for (int r = 0; r < 4; r++)
#pragma unroll
        for (int s = 0; s < 4; s++)
            g_gcp[(ic*N_ + n)*4096 + (ty*4 + r)*C_ + tx*4 + s] = acc[r][s];
}

// ============ K3a: reduce 16 partials + softmax over n ============
__global__ void k_gc_softmax()
{
    int cd = blockIdx.x * 256 + threadIdx.x;
    float v[N_];
    float mx = -1e30f;
#pragma unroll
    for (int n = 0; n < N_; n++) {
        float s = 0.f;
#pragma unroll
        for (int ic = 0; ic < 16; ic++) s += g_gcp[(ic*N_ + n)*4096 + cd];
        v[n] = s; mx = fmaxf(mx, s);
    }
    float s = 0.f;
#pragma unroll
    for (int n = 0; n < N_; n++) { v[n] = __expf(v[n] - mx); s += v[n]; }
    float inv = 1.f / s;
#pragma unroll
    for (int n = 0; n < N_; n++) g_gc[n*4096 + cd] = v[n] * inv;
}

// ============ K3b: a_c = m_c @ v — FMA2 GEMM, grid (N_,16) ============
__global__ __launch_bounds__(256) void k_ac()
{
    __shared__ float sv[64*64];   // [d][i] 16 KB
    __shared__ float sm[64*64];   // 16 KB
    int n = blockIdx.x;
    int i0 = blockIdx.y << 6;
    int tid = threadIdx.x, ty = tid >> 4, tx = tid & 15;
    int c0 = ty * 4;

    for (int k = tid; k < 1024; k += 256) {
        int d = k >> 4, f = k & 15;
        ((float4*)sv)[k] = ((const float4*)(g_rv + (n*C_ + d)*HW + i0))[f];
    }
    for (int k = tid; k < 4096; k += 256) sm[k] = g_gc[n*4096 + k];
    __syncthreads();

    ull acc[4][2];
#pragma unroll
    for (int r = 0; r < 4; r++) { acc[r][0] = 0ULL; acc[r][1] = 0ULL; }

#pragma unroll 8
    for (int d = 0; d < C_; d++) {
        float4 b0 = *(const float4*)&sv[d*64 + tx*4];
        ull bv0, bv1;
        f4_to_2ull(b0, bv0, bv1);
#pragma unroll
        for (int r = 0; r < 4; r++) {
            float a = sm[(c0 + r)*C_ + d];
            ull ap = pack2(a, a);
            fma2(acc[r][0], ap, bv0);
            fma2(acc[r][1], ap, bv1);
        }
    }
#pragma unroll
    for (int r = 0; r < 4; r++) {
        float2 u0 = unpack2(acc[r][0]), u1 = unpack2(acc[r][1]);
        *(float4*)&g_s[(n*C_ + c0 + r)*HW + i0 + tx*4] =
            make_float4(u0.x, u0.y, u1.x, u1.y);
    }
}

// ============ K4: e = exp(q^T k) → fp16 — dup-q FMA2 GEMM, grid (8,8,N_) ============
__global__ __launch_bounds__(256, 2) void k_ms()
{
    __shared__ float sqd[32*256];
    __shared__ float sk[32*128];
    int n  = blockIdx.z;
    int i0 = blockIdx.x << 7, j0 = blockIdx.y << 7;
    int tid = threadIdx.x, ty = tid >> 4, tx = tid & 15;
    unsigned sq_base = (unsigned)__cvta_generic_to_shared(sqd) + ty*64;
    unsigned sk_base = (unsigned)__cvta_generic_to_shared(sk)  + tx*32;

    ull acc[8][4];
#pragma unroll
    for (int r = 0; r < 8; r++)
#pragma unroll
        for (int s = 0; s < 4; s++) acc[r][s] = 0ULL;

    for (int cc = 0; cc < C_; cc += 32) {
        __syncthreads();
        const float* qp = g_rq + (n*C_ + cc)*HW + i0;
        const float* kp = g_rk + (n*C_ + cc)*HW + j0;
        for (int k = tid; k < 1024; k += 256) {
            int c = k >> 5, f = k & 31;
            ((float4*)sk)[k] = ((const float4*)(kp + c*HW))[f];
            float4 q4 = ((const float4*)(qp + c*HW))[f];
            ((float4*)sqd)[c*64 + 2*f]     = make_float4(q4.x, q4.x, q4.y, q4.y);
            ((float4*)sqd)[c*64 + 2*f + 1] = make_float4(q4.z, q4.z, q4.w, q4.w);
        }
        __syncthreads();
#pragma unroll 8
        for (int c = 0; c < 32; c++) {
            ull b0, b1, b2, b3;
            lds2(b0, b1, sk_base + c*512);
            lds2(b2, b3, sk_base + c*512 + 16);
            ull a0, a1, a2, a3, a4, a5, a6, a7;
            lds2(a0, a1, sq_base + c*1024);
            lds2(a2, a3, sq_base + c*1024 + 16);
            lds2(a4, a5, sq_base + c*1024 + 32);
            lds2(a6, a7, sq_base + c*1024 + 48);
            fma2(acc[0][0],a0,b0); fma2(acc[0][1],a0,b1); fma2(acc[0][2],a0,b2); fma2(acc[0][3],a0,b3);
            fma2(acc[1][0],a1,b0); fma2(acc[1][1],a1,b1); fma2(acc[1][2],a1,b2); fma2(acc[1][3],a1,b3);
            fma2(acc[2][0],a2,b0); fma2(acc[2][1],a2,b1); fma2(acc[2][2],a2,b2); fma2(acc[2][3],a2,b3);
            fma2(acc[3][0],a3,b0); fma2(acc[3][1],a3,b1); fma2(acc[3][2],a3,b2); fma2(acc[3][3],a3,b3);
            fma2(acc[4][0],a4,b0); fma2(acc[4][1],a4,b1); fma2(acc[4][2],a4,b2); fma2(acc[4][3],a4,b3);
            fma2(acc[5][0],a5,b0); fma2(acc[5][1],a5,b1); fma2(acc[5][2],a5,b2); fma2(acc[5][3],a5,b3);
            fma2(acc[6][0],a6,b0); fma2(acc[6][1],a6,b1); fma2(acc[6][2],a6,b2); fma2(acc[6][3],a6,b3);
            fma2(acc[7][0],a7,b0); fma2(acc[7][1],a7,b1); fma2(acc[7][2],a7,b2); fma2(acc[7][3],a7,b3);
        }
    }
    __half* outp = g_ms + ((size_t)n << 20) + (size_t)(i0 + ty*8)*HW + j0 + tx*8;
#pragma unroll
    for (int r = 0; r < 8; r++) {
        float2 u0 = unpack2(acc[r][0]), u1 = unpack2(acc[r][1]);
        float2 u2 = unpack2(acc[r][2]), u3 = unpack2(acc[r][3]);
        __half2 h0 = __float22half2_rn(make_float2(__expf(u0.x), __expf(u0.y)));
        __half2 h1 = __float22half2_rn(make_float2(__expf(u1.x), __expf(u1.y)));
        __half2 h2 = __float22half2_rn(make_float2(__expf(u2.x), __expf(u2.y)));
        __half2 h3 = __float22half2_rn(make_float2(__expf(u3.x), __expf(u3.y)));
        uint4 u;
        u.x = *(unsigned*)&h0; u.y = *(unsigned*)&h1;
        u.z = *(unsigned*)&h2; u.w = *(unsigned*)&h3;
        *(uint4*)(outp + (size_t)r*HW) = u;
    }
}

// ============ K5: g_inv = 1 / sum_n e — 8 halves/thread, grid 512 ============
__global__ __launch_bounds__(256) void k_sum()
{
    size_t t = (size_t)blockIdx.x * 256 + threadIdx.x;   // uint4 index, 0..131071
    const uint4* base = (const uint4*)g_ms;              // 8 halves per uint4
    float2 acc[4];
#pragma unroll
    for (int m = 0; m < 4; m++) acc[m] = make_float2(0.f, 0.f);
#pragma unroll
    for (int n = 0; n < N_; n++) {
        uint4 u = base[((size_t)n << 17) + t];           // 131072 uint4 per n
        const __half2* h = (const __half2*)&u;
#pragma unroll
        for (int m = 0; m < 4; m++) {
            float2 f0 = __half22float2(h[m]);
            acc[m].x += f0.x; acc[m].y += f0.y;
        }
    }
    float* gp = g_inv + t*8;
#pragma unroll
    for (int m = 0; m < 4; m++) {
        gp[2*m]   = 1.f / acc[m].x;
        gp[2*m+1] = 1.f / acc[m].y;
    }
}

// ============ K6: a_s = P @ v^T — FMA2, grid (8 i-tiles, 2 j-halves, N_) ============
__global__ __launch_bounds__(256, 3) void k_as()
{
    int n  = blockIdx.z;
    int jh = blockIdx.y;
    int i0 = blockIdx.x << 7;
    __shared__ ull   sv2[C_*33];    // [c][jj] v duplicated pairs
    __shared__ float seT[32*132];   // [jj][ii] P^T fp32
    int tid = threadIdx.x, ty = tid >> 4, tx = tid & 15;
    int c0 = ty * 4;
    unsigned se_base = (unsigned)__cvta_generic_to_shared(seT) + tx*32;

    ull acc[4][4];
#pragma unroll
    for (int r = 0; r < 4; r++)
#pragma unroll
        for (int s = 0; s < 4; s++) acc[r][s] = 0ULL;

    const __half* msph = g_ms + ((size_t)n << 20);
    for (int jc = 0; jc < 16; jc++) {
        int j0 = jh*512 + jc*32;
        __syncthreads();
        for (int k = tid; k < 2048; k += 256) {
            int c = k >> 5, jj = k & 31;
            float v = g_rv[(n*C_ + c)*HW + j0 + jj];
            sv2[c*33 + jj] = pack2(v, v);
        }
        for (int k = tid; k < 2048; k += 256) {   // 128 ii x 16 jj2 (half2)
            int ii = k >> 4, jj2 = k & 15;
            int gi = i0 + ii;
            __half2 e2 = *(const __half2*)(msph + (size_t)gi*HW + j0 + jj2*2);
            float2 ef = __half22float2(e2);
            float2 inv2 = *(const float2*)&g_inv[gi*HW + j0 + jj2*2];
            seT[(2*jj2)*132 + ii]   = ef.x * inv2.x;
            seT[(2*jj2+1)*132 + ii] = ef.y * inv2.y;
        }
        __syncthreads();
#pragma unroll 8
        for (int j = 0; j < 32; j++) {
            ull ap[4];
#pragma unroll
            for (int r = 0; r < 4; r++) ap[r] = sv2[(c0 + r)*33 + j];
            ull b0, b1, b2, b3;
            lds2(b0, b1, se_base + j*528);
            lds2(b2, b3, se_base + j*528 + 16);
#pragma unroll
            for (int r = 0; r < 4; r++) {
                fma2(acc[r][0], ap[r], b0);
                fma2(acc[r][1], ap[r], b1);
                fma2(acc[r][2], ap[r], b2);
                fma2(acc[r][3], ap[r], b3);
            }
        }
    }
    if (jh == 0) {
#pragma unroll
        for (int r = 0; r < 4; r++) {
            float2 u0 = unpack2(acc[r][0]), u1 = unpack2(acc[r][1]);
            float2 u2 = unpack2(acc[r][2]), u3 = unpack2(acc[r][3]);
            float* gp = g_s + (n*C_ + c0 + r)*HW + i0 + tx*8;
            float4 o0 = *(float4*)gp;
            float4 o1 = *(float4*)(gp + 4);
            o0.x += u0.x; o0.y += u0.y; o0.z += u1.x; o0.w += u1.y;
            o1.x += u2.x; o1.y += u2.y; o1.z += u3.x; o1.w += u3.y;
            *(float4*)gp = o0;
            *(float4*)(gp + 4) = o1;
        }
    } else {
#pragma unroll
        for (int r = 0; r < 4; r++) {
            float2 u0 = unpack2(acc[r][0]), u1 = unpack2(acc[r][1]);
            float2 u2 = unpack2(acc[r][2]), u3 = unpack2(acc[r][3]);
            float* gp = g_sp + (n*C_ + c0 + r)*HW + i0 + tx*8;
            *(float4*)gp       = make_float4(u0.x, u0.y, u1.x, u1.y);
            *(float4*)(gp + 4) = make_float4(u2.x, u2.y, u3.x, u3.y);
        }
    }
}

// ============ K7: Xe = relu(tconv3(g_s + g_sp)) — FMA2, grid (N_,8) ============
__global__ __launch_bounds__(256) void k_tconv(const float* __restrict__ wX,
                                               const float* __restrict__ bX)
{
    __shared__ float sw[4096];
    __shared__ float ss[32*128];
    int n = blockIdx.x, b = n >> 3, t = n & 7;
    int i0 = blockIdx.y << 7;
    int tid = threadIdx.x, ty = tid >> 4, tx = tid & 15;
    int o0 = ty * 4;

    ull acc[4][4];
#pragma unroll
    for (int r = 0; r < 4; r++) {
        float bi = bX[o0 + r];
        ull bp = pack2(bi, bi);
#pragma unroll
        for (int s = 0; s < 4; s++) acc[r][s] = bp;
    }

    for (int kt = 0; kt < 3; kt++) {
        int t2 = t + kt - 1;
        if (t2 < 0 || t2 >= TT_) continue;
        __syncthreads();
        for (int k = tid; k < 4096; k += 256) sw[k] = wX[k*3 + kt];
        for (int cc = 0; cc < 2; cc++) {
            __syncthreads();
            size_t off = (size_t)((b*TT_ + t2)*C_ + cc*32)*HW + i0;
            for (int k = tid; k < 1024; k += 256) {
                int c = k >> 5, f = k & 31;
                float4 v0 = ((const float4*)(g_s  + off + c*HW))[f];
                float4 v1 = ((const float4*)(g_sp + off + c*HW))[f];
                ((float4*)ss)[k] = make_float4(v0.x+v1.x, v0.y+v1.y, v0.z+v1.z, v0.w+v1.w);
            }
            __syncthreads();
#pragma unroll 4
            for (int c = 0; c < 32; c++) {
                ull ap[4];
#pragma unroll
                for (int r = 0; r < 4; r++) {
                    float a = sw[(o0 + r)*C_ + cc*32 + c];
                    ap[r] = pack2(a, a);
                }
                float4 b0 = *(const float4*)&ss[c*128 + tx*8];
                float4 b1 = *(const float4*)&ss[c*128 + tx*8 + 4];
                ull bv0, bv1, bv2, bv3;
                f4_to_2ull(b0, bv0, bv1);
                f4_to_2ull(b1, bv2, bv3);
#pragma unroll
                for (int r = 0; r < 4; r++) {
                    fma2(acc[r][0], ap[r], bv0);
                    fma2(acc[r][1], ap[r], bv1);
                    fma2(acc[r][2], ap[r], bv2);
                    fma2(acc[r][3], ap[r], bv3);
                }
            }
        }
    }
#pragma unroll
    for (int r = 0; r < 4; r++) {
        float2 u0 = unpack2(acc[r][0]), u1 = unpack2(acc[r][1]);
        float2 u2 = unpack2(acc[r][2]), u3 = unpack2(acc[r][3]);
        float* gp = g_xe + (n*C_ + o0 + r)*HW + i0 + tx*8;
        *(float4*)gp       = make_float4(fmaxf(u0.x,0.f), fmaxf(u0.y,0.f),
                                         fmaxf(u1.x,0.f), fmaxf(u1.y,0.f));
        *(float4*)(gp + 4) = make_float4(fmaxf(u2.x,0.f), fmaxf(u2.y,0.f),
                                         fmaxf(u3.x,0.f), fmaxf(u3.y,0.f));
    }
}

// ============ K8a: temporal score partials, grid (B_,8) ============
__global__ __launch_bounds__(256) void k_mtp()
{
    int b = blockIdx.x, dc = blockIdx.y;
    int tid = threadIdx.x, lane = tid & 31, warp = tid >> 5;
    int d0 = dc * 8192;
    float acc[64];
#pragma unroll
    for (int a = 0; a < 64; a++) acc[a] = 0.f;

    for (int m = 0; m < 32; m++) {
        int d = d0 + m*256 + tid;
        float v[8];
#pragma unroll
        for (int t = 0; t < 8; t++) v[t] = g_xe[(size_t)(b*TT_ + t)*CHW + d];
#pragma unroll
        for (int t = 0; t < 8; t++)
#pragma unroll
            for (int s = 0; s < 8; s++) acc[t*8 + s] = fmaf(v[t], v[s], acc[t*8 + s]);
    }
#pragma unroll
    for (int a = 0; a < 64; a++) {
#pragma unroll
        for (int off = 16; off > 0; off >>= 1)
            acc[a] += __shfl_xor_sync(0xffffffffu, acc[a], off);
    }
    __shared__ float red[8][64];
    if (lane == 0)
        for (int a = 0; a < 64; a++) red[warp][a] = acc[a];
    __syncthreads();
    if (tid < 64) {
        float s = 0.f;
#pragma unroll
        for (int w = 0; w < 8; w++) s += red[w][tid];
        g_mtp[(b*8 + dc)*64 + tid] = s;
    }
}

// ============ K8b: reduce partials + softmax over b ============
__global__ void k_mt_softmax()
{
    __shared__ float sm[B_][64];
    int tid = threadIdx.x;
    int b = tid >> 6, ts = tid & 63;
    float s = 0.f;
#pragma unroll
    for (int dc = 0; dc < 8; dc++) s += g_mtp[(b*8 + dc)*64 + ts];
    sm[b][ts] = s;
    __syncthreads();
    if (tid < 64) {
        float v[B_];
        float mx = -1e30f;
#pragma unroll
        for (int bb = 0; bb < B_; bb++) { v[bb] = sm[bb][tid]; mx = fmaxf(mx, v[bb]); }
        float ss = 0.f;
#pragma unroll
        for (int bb = 0; bb < B_; bb++) { v[bb] = __expf(v[bb] - mx); ss += v[bb]; }
        float inv = 1.f / ss;
#pragma unroll
        for (int bb = 0; bb < B_; bb++) g_mt[bb*64 + tid] = v[bb] * inv;
    }
}

// ============ K8c: out[b,c,t,i] = sum_s m_t[b,t,s] v[b,s,c,i], grid 256 ============
__global__ __launch_bounds__(256) void k_out(float* __restrict__ out)
{
    int bc = blockIdx.x;
    int b = bc >> 6, c = bc & 63;
    __shared__ float smt[64];
    if (threadIdx.x < 64) smt[threadIdx.x] = g_mt[b*64 + threadIdx.x];
    __syncthreads();
    for (int k = 0; k < 4; k++) {
        int i = k*256 + threadIdx.x;
        float v[8];
#pragma unroll
        for (int s = 0; s < 8; s++)
            v[s] = g_rv[(size_t)((b*TT_ + s)*C_ + c)*HW + i];
#pragma unroll
        for (int t = 0; t < 8; t++) {
            float a = 0.f;
#pragma unroll
            for (int s = 0; s < 8; s++) a = fmaf(smt[t*8 + s], v[s], a);
            out[(size_t)((b*C_ + c)*TT_ + t)*HW + i] = a;
        }
    }
}

// ---------------- launch ----------------
extern "C" void kernel_launch(void* const* d_in, const int* in_sizes, int n_in,
                              void* d_out, int out_size)
{
    const float* x  = (const float*)d_in[0];
    const float* wq = (const float*)d_in[1];
    const float* bq = (const float*)d_in[2];
    const float* wk = (const float*)d_in[3];
    const float* bk = (const float*)d_in[4];
    const float* wv = (const float*)d_in[5];
    const float* bv = (const float*)d_in[6];
    const float* wX = (const float*)d_in[7];
    const float* bX = (const float*)d_in[8];
    float* out = (float*)d_out;
    (void)in_sizes; (void)n_in; (void)out_size;

    cudaFuncSetAttribute(k_qkv, cudaFuncAttributeMaxDynamicSharedMemorySize, 49152);

    k_qkv<<<dim3(N_, 8, 3), 256, 49152>>>(x, wq, bq, wk, bk, wv, bv);
    k_gc<<<dim3(N_, 16), 256>>>();
    k_gc_softmax<<<16, 256>>>();
    k_ac<<<dim3(N_, 16), 256>>>();
    k_ms<<<dim3(8, 8, N_), 256>>>();
    k_sum<<<512, 256>>>();
    k_as<<<dim3(8, 2, N_), 256>>>();
    k_tconv<<<dim3(N_, 8), 256>>>(wX, bX);
    k_mtp<<<dim3(B_, 8), 256>>>();
    k_mt_softmax<<<1, 256>>>();
    k_out<<<256, 256>>>(out);
}

// round 8
// speedup vs baseline: 2.7959x; 2.0206x over previous
#include <cuda_runtime.h>
#include <cuda_fp16.h>

// Problem constants: B=4, C=64, T=8, H=32, W=32, O=64
#define B_   4
#define TT_  8
#define N_   32          // B*T
#define C_   64
#define HW   1024        // H*W
#define CHW  65536       // C*HW

typedef unsigned long long ull;

// ---------------- f32x2 helpers ----------------
__device__ __forceinline__ ull pack2(float a, float b) {
    ull r;
    asm("mov.b64 %0,{%1,%2};" : "=l"(r) : "f"(a), "f"(b));
    return r;
}
__device__ __forceinline__ void fma2(ull& d, ull a, ull b) {
    asm("fma.rn.f32x2 %0,%1,%2,%0;" : "+l"(d) : "l"(a), "l"(b));
}
__device__ __forceinline__ float2 unpack2(ull v) {
    float2 f;
    asm("mov.b64 {%0,%1},%2;" : "=f"(f.x), "=f"(f.y) : "l"(v));
    return f;
}
__device__ __forceinline__ void f4_to_2ull(float4 v, ull& lo, ull& hi) {
    lo = pack2(v.x, v.y);
    hi = pack2(v.z, v.w);
}

// ---------------- HMMA m16n8k16 fp16->fp32 ----------------
__device__ __forceinline__ void mma16816(float d[4],
    unsigned a0, unsigned a1, unsigned a2, unsigned a3,
    unsigned b0, unsigned b1)
{
    asm volatile(
        "mma.sync.aligned.m16n8k16.row.col.f32.f16.f16.f32 "
        "{%0,%1,%2,%3},{%4,%5,%6,%7},{%8,%9},{%0,%1,%2,%3};"
        : "+f"(d[0]), "+f"(d[1]), "+f"(d[2]), "+f"(d[3])
        : "r"(a0), "r"(a1), "r"(a2), "r"(a3), "r"(b0), "r"(b1));
}

// ---------------- scratch (device globals; no allocation) ----------------
__device__ __half g_qh[N_*HW*C_];               // 4 MB  q fp16, (n,i,c)
__device__ __half g_kh[N_*HW*C_];               // 4 MB  k fp16, (n,i,c)
__device__ float  g_rv [N_*C_*HW];              // 8 MB  v fp32, (n,c,i)
__device__ __half g_rvh[N_*C_*HW];              // 4 MB  v fp16, (n,c,i)
__device__ float  g_gcp[16*N_*C_*C_];           // 8 MB  channel-score partials
__device__ float  g_gc[N_*C_*C_];               // 512 KB softmaxed channel attn
__device__ __half g_ms[(size_t)N_*HW*HW];       // 64 MB exp(spatial scores)
__device__ float  g_inv[HW*HW];                 // 4 MB  1/sum_n exp
__device__ float  g_s [N_*C_*HW];               // 8 MB  a_c + a_s
__device__ float  g_xe[N_*C_*HW];               // 8 MB  relu(tconv3)
__device__ float  g_mtp[B_*8*64];               // temporal score partials
__device__ float  g_mt[B_*TT_*TT_];             // temporal softmax

// ============ K1: one projection per z: relu(W x + b), grid (N_,8,3) ============
__global__ __launch_bounds__(256) void k_qkv(
    const float* __restrict__ x,
    const float* __restrict__ wq, const float* __restrict__ bq,
    const float* __restrict__ wk, const float* __restrict__ bk,
    const float* __restrict__ wv, const float* __restrict__ bv)
{
    extern __shared__ float dyn[];
    float* sx = dyn;            // 64 x 128
    float* sw = dyn + 8192;     // 64o x 64c
    int n = blockIdx.x, b = n >> 3, t = n & 7;
    int i0 = blockIdx.y << 7;
    int p = blockIdx.z;
    int tid = threadIdx.x, ty = tid >> 4, tx = tid & 15;
    int o0 = ty * 4;

    const float* W  = (p == 0) ? wq : (p == 1) ? wk : wv;
    const float* Bb = (p == 0) ? bq : (p == 1) ? bk : bv;

    for (int k = tid; k < 2048; k += 256) {
        int c = k >> 5, f = k & 31;
        ((float4*)sx)[k] =
            ((const float4*)(x + ((size_t)(b*C_ + c)*TT_ + t)*HW + i0))[f];
    }
    for (int k = tid; k < 4096; k += 256) sw[k] = W[k];
    __syncthreads();

    ull acc[4][4];
#pragma unroll
    for (int r = 0; r < 4; r++) {
        float bi = Bb[o0 + r];
        ull bp = pack2(bi, bi);
#pragma unroll
        for (int s = 0; s < 4; s++) acc[r][s] = bp;
    }
#pragma unroll 4
    for (int c = 0; c < C_; c++) {
        ull ap[4];
#pragma unroll
        for (int r = 0; r < 4; r++) {
            float a = sw[(o0 + r)*C_ + c];
            ap[r] = pack2(a, a);
        }
        float4 b0 = *(const float4*)&sx[c*128 + tx*8];
        float4 b1 = *(const float4*)&sx[c*128 + tx*8 + 4];
        ull bv0, bv1, bv2, bv3;
        f4_to_2ull(b0, bv0, bv1);
        f4_to_2ull(b1, bv2, bv3);
#pragma unroll
        for (int r = 0; r < 4; r++) {
            fma2(acc[r][0], ap[r], bv0);
            fma2(acc[r][1], ap[r], bv1);
            fma2(acc[r][2], ap[r], bv2);
            fma2(acc[r][3], ap[r], bv3);
        }
    }
    // unpack + relu
    float va[4][8];
#pragma unroll
    for (int r = 0; r < 4; r++)
#pragma unroll
        for (int s = 0; s < 4; s++) {
            float2 u = unpack2(acc[r][s]);
            va[r][2*s]   = fmaxf(u.x, 0.f);
            va[r][2*s+1] = fmaxf(u.y, 0.f);
        }

    if (p < 2) {
        // q/k -> fp16 (n, i, c) layout
        __half* Oh = (p == 0) ? g_qh : g_kh;
#pragma unroll
        for (int mi = 0; mi < 8; mi++) {
            __half2 h0 = __floats2half2_rn(va[0][mi], va[1][mi]);
            __half2 h1 = __floats2half2_rn(va[2][mi], va[3][mi]);
            uint2 st;
            st.x = *(unsigned*)&h0;
            st.y = *(unsigned*)&h1;
            *(uint2*)(Oh + ((size_t)(n*HW + i0 + tx*8 + mi))*C_ + o0) = st;
        }
    } else {
        // v -> fp32 (n,c,i) + fp16 (n,c,i)
#pragma unroll
        for (int r = 0; r < 4; r++) {
            float* gp = g_rv + (size_t)(n*C_ + o0 + r)*HW + i0 + tx*8;
            *(float4*)gp       = make_float4(va[r][0], va[r][1], va[r][2], va[r][3]);
            *(float4*)(gp + 4) = make_float4(va[r][4], va[r][5], va[r][6], va[r][7]);
            __half2 h0 = __floats2half2_rn(va[r][0], va[r][1]);
            __half2 h1 = __floats2half2_rn(va[r][2], va[r][3]);
            __half2 h2 = __floats2half2_rn(va[r][4], va[r][5]);
            __half2 h3 = __floats2half2_rn(va[r][6], va[r][7]);
            uint4 u;
            u.x = *(unsigned*)&h0; u.y = *(unsigned*)&h1;
            u.z = *(unsigned*)&h2; u.w = *(unsigned*)&h3;
            *(uint4*)(g_rvh + (size_t)(n*C_ + o0 + r)*HW + i0 + tx*8) = u;
        }
    }
}

// ============ K2: channel score partials from fp16 (i,c), grid (N_,16) ============
__global__ __launch_bounds__(256) void k_gc()
{
    int n = blockIdx.x, ic = blockIdx.y;
    int i0 = ic << 6;
    __shared__ float sq[64*68];
    __shared__ float sk[64*68];
    int tid = threadIdx.x, ty = tid >> 4, tx = tid & 15;

    for (int it = 0; it < 2; it++) {
        int idx = tid + it*256;            // 0..511
        int ii = idx >> 3, f = idx & 7;
        uint4 uq = *(const uint4*)(g_qh + ((size_t)(n*HW + i0 + ii))*C_ + f*8);
        uint4 uk = *(const uint4*)(g_kh + ((size_t)(n*HW + i0 + ii))*C_ + f*8);
        const __half2* hq = (const __half2*)&uq;
        const __half2* hk = (const __half2*)&uk;
#pragma unroll
        for (int m = 0; m < 4; m++) {
            float2 fq = __half22float2(hq[m]);
            float2 fk = __half22float2(hk[m]);
            sq[ii*68 + f*8 + 2*m]     = fq.x;
            sq[ii*68 + f*8 + 2*m + 1] = fq.y;
            sk[ii*68 + f*8 + 2*m]     = fk.x;
            sk[ii*68 + f*8 + 2*m + 1] = fk.y;
        }
    }
    __syncthreads();

    float acc[4][4];
#pragma unroll
    for (int r = 0; r < 4; r++)
#pragma unroll
        for (int s = 0; s < 4; s++) acc[r][s] = 0.f;

    for (int ii = 0; ii < 64; ii++) {
        float4 a4 = *(const float4*)&sq[ii*68 + ty*4];
        float4 b4 = *(const float4*)&sk[ii*68 + tx*4];
        float a[4] = {a4.x, a4.y, a4.z, a4.w};
        float bb[4] = {b4.x, b4.y, b4.z, b4.w};
#pragma unroll
        for (int r = 0; r < 4; r++)
#pragma unroll
            for (int s = 0; s < 4; s++) acc[r][s] = fmaf(a[r], bb[s], acc[r][s]);
    }
#pragma unroll
    for (int r = 0; r < 4; r++)
#pragma unroll
        for (int s = 0; s < 4; s++)
            g_gcp[(ic*N_ + n)*4096 + (ty*4 + r)*C_ + tx*4 + s] = acc[r][s];
}

// ============ K3a: reduce 16 partials + softmax over n ============
__global__ void k_gc_softmax()
{
    int cd = blockIdx.x * 256 + threadIdx.x;
    float v[N_];
    float mx = -1e30f;
#pragma unroll
    for (int n = 0; n < N_; n++) {
        float s = 0.f;
#pragma unroll
        for (int ic = 0; ic < 16; ic++) s += g_gcp[(ic*N_ + n)*4096 + cd];
        v[n] = s; mx = fmaxf(mx, s);
    }
    float s = 0.f;
#pragma unroll
    for (int n = 0; n < N_; n++) { v[n] = __expf(v[n] - mx); s += v[n]; }
    float inv = 1.f / s;
#pragma unroll
    for (int n = 0; n < N_; n++) g_gc[n*4096 + cd] = v[n] * inv;
}

// ============ K3b: a_c = m_c @ v (fp32) — FMA2, grid (N_,16) ============
__global__ __launch_bounds__(256) void k_ac()
{
    __shared__ float sv[64*64];
    __shared__ float sm[64*64];
    int n = blockIdx.x;
    int i0 = blockIdx.y << 6;
    int tid = threadIdx.x, ty = tid >> 4, tx = tid & 15;
    int c0 = ty * 4;

    for (int k = tid; k < 1024; k += 256) {
        int d = k >> 4, f = k & 15;
        ((float4*)sv)[k] = ((const float4*)(g_rv + (size_t)(n*C_ + d)*HW + i0))[f];
    }
    for (int k = tid; k < 4096; k += 256) sm[k] = g_gc[n*4096 + k];
    __syncthreads();

    ull acc[4][2];
#pragma unroll
    for (int r = 0; r < 4; r++) { acc[r][0] = 0ULL; acc[r][1] = 0ULL; }

#pragma unroll 8
    for (int d = 0; d < C_; d++) {
        float4 b0 = *(const float4*)&sv[d*64 + tx*4];
        ull bv0, bv1;
        f4_to_2ull(b0, bv0, bv1);
#pragma unroll
        for (int r = 0; r < 4; r++) {
            float a = sm[(c0 + r)*C_ + d];
            ull ap = pack2(a, a);
            fma2(acc[r][0], ap, bv0);
            fma2(acc[r][1], ap, bv1);
        }
    }
#pragma unroll
    for (int r = 0; r < 4; r++) {
        float2 u0 = unpack2(acc[r][0]), u1 = unpack2(acc[r][1]);
        *(float4*)&g_s[(size_t)(n*C_ + c0 + r)*HW + i0 + tx*4] =
            make_float4(u0.x, u0.y, u1.x, u1.y);
    }
}

// ============ K4: e = exp(q^T k) via HMMA — grid (8,8,N_) x 256 ============
// smem: sQ[128][72], sK[128][72] halves (36.9 KB). K=c=64 in one shot.
__global__ __launch_bounds__(256, 2) void k_ms()
{
    __shared__ __half sQ[128*72];
    __shared__ __half sK[128*72];
    int n  = blockIdx.z;
    int i0 = blockIdx.x << 7, j0 = blockIdx.y << 7;
    int tid = threadIdx.x;
    int w = tid >> 5, lane = tid & 31;
    int g = lane >> 2, t = lane & 3;
    int wi = w >> 2, wj = w & 3;            // warp grid 2(i) x 4(j)
    int i_w = wi * 64, j_w = wj * 32;

    for (int it = 0; it < 4; it++) {
        int idx = tid + it*256;             // 0..1023
        int ii = idx >> 3, f = idx & 7;
        *(uint4*)&sQ[ii*72 + f*8] =
            *(const uint4*)(g_qh + ((size_t)(n*HW + i0 + ii))*C_ + f*8);
        *(uint4*)&sK[ii*72 + f*8] =
            *(const uint4*)(g_kh + ((size_t)(n*HW + j0 + ii))*C_ + f*8);
    }
    __syncthreads();

    float acc[4][4][4];                     // [m][nt][4]
#pragma unroll
    for (int m = 0; m < 4; m++)
#pragma unroll
        for (int nt = 0; nt < 4; nt++)
#pragma unroll
            for (int e = 0; e < 4; e++) acc[m][nt][e] = 0.f;

#pragma unroll
    for (int ks = 0; ks < 4; ks++) {
        unsigned a[4][4], bfr[4][2];
#pragma unroll
        for (int m = 0; m < 4; m++) {
            int r0 = i_w + m*16 + g;
            int col = ks*16 + t*2;
            a[m][0] = *(const unsigned*)&sQ[r0*72 + col];
            a[m][1] = *(const unsigned*)&sQ[(r0+8)*72 + col];
            a[m][2] = *(const unsigned*)&sQ[r0*72 + col + 8];
            a[m][3] = *(const unsigned*)&sQ[(r0+8)*72 + col + 8];
        }
#pragma unroll
        for (int nt = 0; nt < 4; nt++) {
            int jr = j_w + nt*8 + g;
            int col = ks*16 + t*2;
            bfr[nt][0] = *(const unsigned*)&sK[jr*72 + col];
            bfr[nt][1] = *(const unsigned*)&sK[jr*72 + col + 8];
        }
#pragma unroll
        for (int m = 0; m < 4; m++)
#pragma unroll
            for (int nt = 0; nt < 4; nt++)
                mma16816(acc[m][nt], a[m][0], a[m][1], a[m][2], a[m][3],
                         bfr[nt][0], bfr[nt][1]);
    }

    __half* outp = g_ms + ((size_t)n << 20);
#pragma unroll
    for (int m = 0; m < 4; m++) {
#pragma unroll
        for (int nt = 0; nt < 4; nt++) {
            int ir0 = i0 + i_w + m*16 + g;
            int j   = j0 + j_w + nt*8 + t*2;
            __half2 h0 = __floats2half2_rn(__expf(acc[m][nt][0]), __expf(acc[m][nt][1]));
            __half2 h1 = __floats2half2_rn(__expf(acc[m][nt][2]), __expf(acc[m][nt][3]));
            *(unsigned*)(outp + (size_t)ir0*HW + j)     = *(unsigned*)&h0;
            *(unsigned*)(outp + (size_t)(ir0+8)*HW + j) = *(unsigned*)&h1;
        }
    }
}

// ============ K5: g_inv = 1 / sum_n e — 8 halves/thread, grid 512 ============
__global__ __launch_bounds__(256) void k_sum()
{
    size_t t = (size_t)blockIdx.x * 256 + threadIdx.x;   // uint4 index, 0..131071
    const uint4* base = (const uint4*)g_ms;
    float2 acc[4];
#pragma unroll
    for (int m = 0; m < 4; m++) acc[m] = make_float2(0.f, 0.f);
#pragma unroll
    for (int n = 0; n < N_; n++) {
        uint4 u = base[((size_t)n << 17) + t];
        const __half2* h = (const __half2*)&u;
#pragma unroll
        for (int m = 0; m < 4; m++) {
            float2 f0 = __half22float2(h[m]);
            acc[m].x += f0.x; acc[m].y += f0.y;
        }
    }
    float* gp = g_inv + t*8;
#pragma unroll
    for (int m = 0; m < 4; m++) {
        gp[2*m]   = 1.f / acc[m].x;
        gp[2*m+1] = 1.f / acc[m].y;
    }
}

// ============ K6: a_s = V @ P^T via HMMA; g_s += — grid (16,N_) x 256 ============
// Block: 64c x 64i, j looped in 16 chunks of 64. smem sV[64][72], sP[64][72].
__global__ __launch_bounds__(256, 4) void k_as()
{
    __shared__ __half sV[64*72];
    __shared__ __half sP[64*72];
    int n  = blockIdx.y;
    int i0 = blockIdx.x << 6;
    int tid = threadIdx.x;
    int w = tid >> 5, lane = tid & 31;
    int g = lane >> 2, t = lane & 3;
    int wc = w >> 2, wi = w & 3;            // warp grid 2(c) x 4(i)
    int c_w = wc * 32, i_w = wi * 16;

    float acc[2][2][4];                     // [m][nt][4]
#pragma unroll
    for (int m = 0; m < 2; m++)
#pragma unroll
        for (int nt = 0; nt < 2; nt++)
#pragma unroll
            for (int e = 0; e < 4; e++) acc[m][nt][e] = 0.f;

    const __half* msph = g_ms + ((size_t)n << 20);
    for (int jc = 0; jc < 16; jc++) {
        int j0 = jc << 6;
        __syncthreads();
        for (int it = 0; it < 2; it++) {
            int idx = tid + it*256;         // 0..511
            int row = idx >> 3, f = idx & 7;
            // V tile
            *(uint4*)&sV[row*72 + f*8] =
                *(const uint4*)(g_rvh + (size_t)(n*C_ + row)*HW + j0 + f*8);
            // P tile = e * inv
            int gi = i0 + row;
            uint4 ue = *(const uint4*)(msph + (size_t)gi*HW + j0 + f*8);
            const __half2* he = (const __half2*)&ue;
            const float4* ip = (const float4*)&g_inv[gi*HW + j0 + f*8];
            float4 iv0 = ip[0], iv1 = ip[1];
            float2 e0 = __half22float2(he[0]);
            float2 e1 = __half22float2(he[1]);
            float2 e2 = __half22float2(he[2]);
            float2 e3 = __half22float2(he[3]);
            __half2 p0 = __floats2half2_rn(e0.x*iv0.x, e0.y*iv0.y);
            __half2 p1 = __floats2half2_rn(e1.x*iv0.z, e1.y*iv0.w);
            __half2 p2 = __floats2half2_rn(e2.x*iv1.x, e2.y*iv1.y);
            __half2 p3 = __floats2half2_rn(e3.x*iv1.z, e3.y*iv1.w);
            uint4 up;
            up.x = *(unsigned*)&p0; up.y = *(unsigned*)&p1;
            up.z = *(unsigned*)&p2; up.w = *(unsigned*)&p3;
            *(uint4*)&sP[row*72 + f*8] = up;
        }
        __syncthreads();

#pragma unroll
        for (int ks = 0; ks < 4; ks++) {
            unsigned a[2][4], bfr[2][2];
            int col = ks*16 + t*2;
#pragma unroll
            for (int m = 0; m < 2; m++) {
                int r0 = c_w + m*16 + g;
                a[m][0] = *(const unsigned*)&sV[r0*72 + col];
                a[m][1] = *(const unsigned*)&sV[(r0+8)*72 + col];
                a[m][2] = *(const unsigned*)&sV[r0*72 + col + 8];
                a[m][3] = *(const unsigned*)&sV[(r0+8)*72 + col + 8];
            }
#pragma unroll
            for (int nt = 0; nt < 2; nt++) {
                int ir = i_w + nt*8 + g;
                bfr[nt][0] = *(const unsigned*)&sP[ir*72 + col];
                bfr[nt][1] = *(const unsigned*)&sP[ir*72 + col + 8];
            }
#pragma unroll
            for (int m = 0; m < 2; m++)
#pragma unroll
                for (int nt = 0; nt < 2; nt++)
                    mma16816(acc[m][nt], a[m][0], a[m][1], a[m][2], a[m][3],
                             bfr[nt][0], bfr[nt][1]);
        }
    }

    // accumulate into g_s (holds a_c); disjoint tiles -> no races
#pragma unroll
    for (int m = 0; m < 2; m++) {
#pragma unroll
        for (int nt = 0; nt < 2; nt++) {
            int c0 = c_w + m*16 + g;
            int i  = i0 + i_w + nt*8 + t*2;
            float2* p0 = (float2*)&g_s[(size_t)(n*C_ + c0)*HW + i];
            float2 v0 = *p0;
            v0.x += acc[m][nt][0]; v0.y += acc[m][nt][1];
            *p0 = v0;
            float2* p1 = (float2*)&g_s[(size_t)(n*C_ + c0 + 8)*HW + i];
            float2 v1 = *p1;
            v1.x += acc[m][nt][2]; v1.y += acc[m][nt][3];
            *p1 = v1;
        }
    }
}

// ============ K7: Xe = relu(tconv3(g_s)) — FMA2, grid (N_,8) ============
__global__ __launch_bounds__(256) void k_tconv(const float* __restrict__ wX,
                                               const float* __restrict__ bX)
{
    __shared__ float sw[4096];
    __shared__ float ss[32*128];
    int n = blockIdx.x, b = n >> 3, t = n & 7;
    int i0 = blockIdx.y << 7;
    int tid = threadIdx.x, ty = tid >> 4, tx = tid & 15;
    int o0 = ty * 4;

    ull acc[4][4];
#pragma unroll
    for (int r = 0; r < 4; r++) {
        float bi = bX[o0 + r];
        ull bp = pack2(bi, bi);
#pragma unroll
        for (int s = 0; s < 4; s++) acc[r][s] = bp;
    }

    for (int kt = 0; kt < 3; kt++) {
        int t2 = t + kt - 1;
        if (t2 < 0 || t2 >= TT_) continue;
        __syncthreads();
        for (int k = tid; k < 4096; k += 256) sw[k] = wX[k*3 + kt];
        for (int cc = 0; cc < 2; cc++) {
            __syncthreads();
            size_t off = (size_t)((b*TT_ + t2)*C_ + cc*32)*HW + i0;
            for (int k = tid; k < 1024; k += 256) {
                int c = k >> 5, f = k & 31;
                ((float4*)ss)[k] = ((const float4*)(g_s + off + c*HW))[f];
            }
            __syncthreads();
#pragma unroll 4
            for (int c = 0; c < 32; c++) {
                ull ap[4];
#pragma unroll
                for (int r = 0; r < 4; r++) {
                    float a = sw[(o0 + r)*C_ + cc*32 + c];
                    ap[r] = pack2(a, a);
                }
                float4 b0 = *(const float4*)&ss[c*128 + tx*8];
                float4 b1 = *(const float4*)&ss[c*128 + tx*8 + 4];
                ull bv0, bv1, bv2, bv3;
                f4_to_2ull(b0, bv0, bv1);
                f4_to_2ull(b1, bv2, bv3);
#pragma unroll
                for (int r = 0; r < 4; r++) {
                    fma2(acc[r][0], ap[r], bv0);
                    fma2(acc[r][1], ap[r], bv1);
                    fma2(acc[r][2], ap[r], bv2);
                    fma2(acc[r][3], ap[r], bv3);
                }
            }
        }
    }
#pragma unroll
    for (int r = 0; r < 4; r++) {
        float2 u0 = unpack2(acc[r][0]), u1 = unpack2(acc[r][1]);
        float2 u2 = unpack2(acc[r][2]), u3 = unpack2(acc[r][3]);
        float* gp = g_xe + (size_t)(n*C_ + o0 + r)*HW + i0 + tx*8;
        *(float4*)gp       = make_float4(fmaxf(u0.x,0.f), fmaxf(u0.y,0.f),
                                         fmaxf(u1.x,0.f), fmaxf(u1.y,0.f));
        *(float4*)(gp + 4) = make_float4(fmaxf(u2.x,0.f), fmaxf(u2.y,0.f),
                                         fmaxf(u3.x,0.f), fmaxf(u3.y,0.f));
    }
}

// ============ K8a: temporal score partials, grid (B_,8) ============
__global__ __launch_bounds__(256) void k_mtp()
{
    int b = blockIdx.x, dc = blockIdx.y;
    int tid = threadIdx.x, lane = tid & 31, warp = tid >> 5;
    int d0 = dc * 8192;
    float acc[64];
#pragma unroll
    for (int a = 0; a < 64; a++) acc[a] = 0.f;

    for (int m = 0; m < 32; m++) {
        int d = d0 + m*256 + tid;
        float v[8];
#pragma unroll
        for (int t = 0; t < 8; t++) v[t] = g_xe[(size_t)(b*TT_ + t)*CHW + d];
#pragma unroll
        for (int t = 0; t < 8; t++)
#pragma unroll
            for (int s = 0; s < 8; s++) acc[t*8 + s] = fmaf(v[t], v[s], acc[t*8 + s]);
    }
#pragma unroll
    for (int a = 0; a < 64; a++) {
#pragma unroll
        for (int off = 16; off > 0; off >>= 1)
            acc[a] += __shfl_xor_sync(0xffffffffu, acc[a], off);
    }
    __shared__ float red[8][64];
    if (lane == 0)
        for (int a = 0; a < 64; a++) red[warp][a] = acc[a];
    __syncthreads();
    if (tid < 64) {
        float s = 0.f;
#pragma unroll
        for (int w = 0; w < 8; w++) s += red[w][tid];
        g_mtp[(b*8 + dc)*64 + tid] = s;
    }
}

// ============ K8b: reduce partials + softmax over b ============
__global__ void k_mt_softmax()
{
    __shared__ float sm[B_][64];
    int tid = threadIdx.x;
    int b = tid >> 6, ts = tid & 63;
    float s = 0.f;
#pragma unroll
    for (int dc = 0; dc < 8; dc++) s += g_mtp[(b*8 + dc)*64 + ts];
    sm[b][ts] = s;
    __syncthreads();
    if (tid < 64) {
        float v[B_];
        float mx = -1e30f;
#pragma unroll
        for (int bb = 0; bb < B_; bb++) { v[bb] = sm[bb][tid]; mx = fmaxf(mx, v[bb]); }
        float ss = 0.f;
#pragma unroll
        for (int bb = 0; bb < B_; bb++) { v[bb] = __expf(v[bb] - mx); ss += v[bb]; }
        float inv = 1.f / ss;
#pragma unroll
        for (int bb = 0; bb < B_; bb++) g_mt[bb*64 + tid] = v[bb] * inv;
    }
}

// ============ K8c: out[b,c,t,i] = sum_s m_t[b,t,s] v[b,s,c,i], grid 256 ============
__global__ __launch_bounds__(256) void k_out(float* __restrict__ out)
{
    int bc = blockIdx.x;
    int b = bc >> 6, c = bc & 63;
    __shared__ float smt[64];
    if (threadIdx.x < 64) smt[threadIdx.x] = g_mt[b*64 + threadIdx.x];
    __syncthreads();
    for (int k = 0; k < 4; k++) {
        int i = k*256 + threadIdx.x;
        float v[8];
#pragma unroll
        for (int s = 0; s < 8; s++)
            v[s] = g_rv[(size_t)((b*TT_ + s)*C_ + c)*HW + i];
#pragma unroll
        for (int t = 0; t < 8; t++) {
            float a = 0.f;
#pragma unroll
            for (int s = 0; s < 8; s++) a = fmaf(smt[t*8 + s], v[s], a);
            out[(size_t)((b*C_ + c)*TT_ + t)*HW + i] = a;
        }
    }
}

// ---------------- launch ----------------
extern "C" void kernel_launch(void* const* d_in, const int* in_sizes, int n_in,
                              void* d_out, int out_size)
{
    const float* x  = (const float*)d_in[0];
    const float* wq = (const float*)d_in[1];
    const float* bq = (const float*)d_in[2];
    const float* wk = (const float*)d_in[3];
    const float* bk = (const float*)d_in[4];
    const float* wv = (const float*)d_in[5];
    const float* bv = (const float*)d_in[6];
    const float* wX = (const float*)d_in[7];
    const float* bX = (const float*)d_in[8];
    float* out = (float*)d_out;
    (void)in_sizes; (void)n_in; (void)out_size;

    cudaFuncSetAttribute(k_qkv, cudaFuncAttributeMaxDynamicSharedMemorySize, 49152);

    k_qkv<<<dim3(N_, 8, 3), 256, 49152>>>(x, wq, bq, wk, bk, wv, bv);
    k_gc<<<dim3(N_, 16), 256>>>();
    k_gc_softmax<<<16, 256>>>();
    k_ac<<<dim3(N_, 16), 256>>>();
    k_ms<<<dim3(8, 8, N_), 256>>>();
    k_sum<<<512, 256>>>();
    k_as<<<dim3(16, N_), 256>>>();
    k_tconv<<<dim3(N_, 8), 256>>>(wX, bX);
    k_mtp<<<dim3(B_, 8), 256>>>();
    k_mt_softmax<<<1, 256>>>();
    k_out<<<256, 256>>>(out);
}